// round 1
// baseline (speedup 1.0000x reference)
#include <cuda_runtime.h>
#include <math.h>

#define N_RAYS 32768
#define N_SAMPLES 1048576
#define HID 64
#define TPB 128

// Scratch (device globals; no allocation anywhere)
__device__ float g_sigma_dt[N_SAMPLES];
__device__ float g_rgb[N_SAMPLES * 3];
__device__ int   g_off[N_RAYS + 1];

// ---------------------------------------------------------------------------
// Per-ray segment offsets: ray_indices is sorted, so offset[r] = lower_bound(r).
// offset[N_RAYS] = N_SAMPLES. Empty rays get zero-length spans.
// ---------------------------------------------------------------------------
__global__ void offsets_kernel(const int* __restrict__ ri) {
    int r = blockIdx.x * 256 + threadIdx.x;
    if (r > N_RAYS) return;
    int lo = 0, hi = N_SAMPLES;
    while (lo < hi) {
        int m = (lo + hi) >> 1;
        if (ri[m] < r) lo = m + 1; else hi = m;
    }
    g_off[r] = lo;
}

// ---------------------------------------------------------------------------
// MLP kernel: one thread per sample. Both MLPs (density + rgb).
// Fused layer1->layer2: h_k produced and consumed inside the k loop, so only
// the 64 layer-2 accumulators stay live. Weights live in shared memory and
// are read via broadcast LDS (all lanes same address -> conflict-free).
// ---------------------------------------------------------------------------
__global__ void __launch_bounds__(TPB) mlp_kernel(
    const float* __restrict__ rays_o, const float* __restrict__ rays_d,
    const float* __restrict__ t_starts, const float* __restrict__ t_ends,
    const int*   __restrict__ ray_indices,
    const float* __restrict__ Wd1, const float* __restrict__ bd1,
    const float* __restrict__ Wd2, const float* __restrict__ bd2,
    const float* __restrict__ Wd3, const float* __restrict__ bd3,
    const float* __restrict__ Wr1, const float* __restrict__ br1,
    const float* __restrict__ Wr2, const float* __restrict__ br2,
    const float* __restrict__ Wr3, const float* __restrict__ br3)
{
    __shared__ float sWd2[HID * HID];
    __shared__ float sWr2[HID * HID];
    __shared__ float sWd1[3 * HID], sWr1[3 * HID], sWr3[HID * 3];
    __shared__ float sWd3[HID];
    __shared__ float sbd1[HID], sbd2[HID], sbr1[HID], sbr2[HID];
    __shared__ float sbd3, sbr3[3];

    const int t = threadIdx.x;
    for (int i = t; i < HID * HID; i += TPB) { sWd2[i] = Wd2[i]; sWr2[i] = Wr2[i]; }
    for (int i = t; i < 3 * HID; i += TPB)  { sWd1[i] = Wd1[i]; sWr1[i] = Wr1[i]; sWr3[i] = Wr3[i]; }
    if (t < HID) { sWd3[t] = Wd3[t]; sbd1[t] = bd1[t]; sbd2[t] = bd2[t]; sbr1[t] = br1[t]; sbr2[t] = br2[t]; }
    if (t == 0) sbd3 = bd3[0];
    if (t < 3)  sbr3[t] = br3[t];
    __syncthreads();

    const int i  = blockIdx.x * TPB + t;     // grid sized so i < N_SAMPLES always
    const int ri = ray_indices[i];
    const float ts  = t_starts[i];
    const float te  = t_ends[i];
    const float mid = 0.5f * (ts + te);
    const float p0 = fmaf(rays_d[ri * 3 + 0], mid, rays_o[ri * 3 + 0]);
    const float p1 = fmaf(rays_d[ri * 3 + 1], mid, rays_o[ri * 3 + 1]);
    const float p2 = fmaf(rays_d[ri * 3 + 2], mid, rays_o[ri * 3 + 2]);

    float acc[HID];

    // ======================= density MLP =======================
    #pragma unroll
    for (int j = 0; j < HID; j++) acc[j] = sbd2[j];

    #pragma unroll 4
    for (int k = 0; k < HID; k++) {
        float hk = sbd1[k];
        hk = fmaf(p0, sWd1[k],           hk);
        hk = fmaf(p1, sWd1[HID + k],     hk);
        hk = fmaf(p2, sWd1[2 * HID + k], hk);
        hk = fmaxf(hk, 0.0f);
        const float4* wr = reinterpret_cast<const float4*>(sWd2 + k * HID);
        #pragma unroll
        for (int j = 0; j < HID / 4; j++) {
            float4 w = wr[j];
            acc[4 * j + 0] = fmaf(hk, w.x, acc[4 * j + 0]);
            acc[4 * j + 1] = fmaf(hk, w.y, acc[4 * j + 1]);
            acc[4 * j + 2] = fmaf(hk, w.z, acc[4 * j + 2]);
            acc[4 * j + 3] = fmaf(hk, w.w, acc[4 * j + 3]);
        }
    }
    float sl = sbd3;
    #pragma unroll
    for (int k = 0; k < HID; k++) {
        float h = fmaxf(acc[k], 0.0f);
        sl = fmaf(h, sWd3[k], sl);
    }
    // stable softplus (matches jax.nn.softplus = logaddexp(x, 0))
    float sigma = fmaxf(sl, 0.0f) + log1pf(expf(-fabsf(sl)));
    g_sigma_dt[i] = sigma * (te - ts);

    // ======================= rgb MLP =======================
    #pragma unroll
    for (int j = 0; j < HID; j++) acc[j] = sbr2[j];

    #pragma unroll 4
    for (int k = 0; k < HID; k++) {
        float hk = sbr1[k];
        hk = fmaf(p0, sWr1[k],           hk);
        hk = fmaf(p1, sWr1[HID + k],     hk);
        hk = fmaf(p2, sWr1[2 * HID + k], hk);
        hk = fmaxf(hk, 0.0f);
        const float4* wr = reinterpret_cast<const float4*>(sWr2 + k * HID);
        #pragma unroll
        for (int j = 0; j < HID / 4; j++) {
            float4 w = wr[j];
            acc[4 * j + 0] = fmaf(hk, w.x, acc[4 * j + 0]);
            acc[4 * j + 1] = fmaf(hk, w.y, acc[4 * j + 1]);
            acc[4 * j + 2] = fmaf(hk, w.z, acc[4 * j + 2]);
            acc[4 * j + 3] = fmaf(hk, w.w, acc[4 * j + 3]);
        }
    }
    float c0 = sbr3[0], c1 = sbr3[1], c2 = sbr3[2];
    #pragma unroll
    for (int k = 0; k < HID; k++) {
        float h = fmaxf(acc[k], 0.0f);
        c0 = fmaf(h, sWr3[k * 3 + 0], c0);
        c1 = fmaf(h, sWr3[k * 3 + 1], c1);
        c2 = fmaf(h, sWr3[k * 3 + 2], c2);
    }
    g_rgb[i * 3 + 0] = 1.0f / (1.0f + expf(-c0));
    g_rgb[i * 3 + 1] = 1.0f / (1.0f + expf(-c1));
    g_rgb[i * 3 + 2] = 1.0f / (1.0f + expf(-c2));
}

// ---------------------------------------------------------------------------
// Render kernel: one warp per ray. Segmented exclusive cumsum of sigma*dt
// within the ray (warp shfl scan with carry across 32-sample chunks),
// weights, segment sums, background composition.
// Output layout: [colors (3R) | distances (R) | opacities (R)].
// ---------------------------------------------------------------------------
__global__ void render_kernel(const float* __restrict__ t_starts,
                              const float* __restrict__ t_ends,
                              float* __restrict__ out)
{
    const int gtid = blockIdx.x * blockDim.x + threadIdx.x;
    const int ray  = gtid >> 5;
    const int lane = threadIdx.x & 31;
    if (ray >= N_RAYS) return;

    const int s = g_off[ray];
    const int e = g_off[ray + 1];

    float carry = 0.0f;                  // cumulative sigma_dt before this chunk
    float op = 0.0f, dist = 0.0f;
    float c0 = 0.0f, c1 = 0.0f, c2 = 0.0f;

    for (int base = s; base < e; base += 32) {
        const int  idx = base + lane;
        const bool v   = (idx < e);
        float sd = v ? g_sigma_dt[idx] : 0.0f;

        // inclusive warp scan
        float x = sd;
        #pragma unroll
        for (int o = 1; o < 32; o <<= 1) {
            float y = __shfl_up_sync(0xffffffffu, x, o);
            if (lane >= o) x += y;
        }
        const float excl = carry + x - sd;      // exclusive prefix within ray
        carry += __shfl_sync(0xffffffffu, x, 31);

        if (v) {
            const float alpha = -expm1f(-sd);           // 1 - exp(-sigma_dt)
            const float w     = expf(-excl) * alpha;    // trans * alpha
            const float mid   = 0.5f * (t_starts[idx] + t_ends[idx]);
            op   += w;
            dist += w * mid;
            c0 += w * g_rgb[idx * 3 + 0];
            c1 += w * g_rgb[idx * 3 + 1];
            c2 += w * g_rgb[idx * 3 + 2];
        }
    }

    // warp reduction
    #pragma unroll
    for (int o = 16; o > 0; o >>= 1) {
        op   += __shfl_down_sync(0xffffffffu, op,   o);
        dist += __shfl_down_sync(0xffffffffu, dist, o);
        c0   += __shfl_down_sync(0xffffffffu, c0,   o);
        c1   += __shfl_down_sync(0xffffffffu, c1,   o);
        c2   += __shfl_down_sync(0xffffffffu, c2,   o);
    }

    if (lane == 0) {
        const float rest = 1.0f - op;
        out[ray * 3 + 0] = c0 + 0.5f * rest;
        out[ray * 3 + 1] = c1 + 0.5f * rest;
        out[ray * 3 + 2] = c2 + 0.5f * rest;
        out[3 * N_RAYS + ray] = dist + 5.0f * rest;
        out[4 * N_RAYS + ray] = op;
    }
}

// ---------------------------------------------------------------------------
extern "C" void kernel_launch(void* const* d_in, const int* in_sizes, int n_in,
                              void* d_out, int out_size)
{
    const float* rays_o      = (const float*)d_in[0];
    const float* rays_d      = (const float*)d_in[1];
    const float* t_starts    = (const float*)d_in[2];
    const float* t_ends      = (const float*)d_in[3];
    const int*   ray_indices = (const int*)  d_in[4];
    const float* W_d1 = (const float*)d_in[5];
    const float* b_d1 = (const float*)d_in[6];
    const float* W_d2 = (const float*)d_in[7];
    const float* b_d2 = (const float*)d_in[8];
    const float* W_d3 = (const float*)d_in[9];
    const float* b_d3 = (const float*)d_in[10];
    const float* W_r1 = (const float*)d_in[11];
    const float* b_r1 = (const float*)d_in[12];
    const float* W_r2 = (const float*)d_in[13];
    const float* b_r2 = (const float*)d_in[14];
    const float* W_r3 = (const float*)d_in[15];
    const float* b_r3 = (const float*)d_in[16];
    float* out = (float*)d_out;

    offsets_kernel<<<(N_RAYS + 1 + 255) / 256, 256>>>(ray_indices);

    mlp_kernel<<<N_SAMPLES / TPB, TPB>>>(
        rays_o, rays_d, t_starts, t_ends, ray_indices,
        W_d1, b_d1, W_d2, b_d2, W_d3, b_d3,
        W_r1, b_r1, W_r2, b_r2, W_r3, b_r3);

    render_kernel<<<(N_RAYS * 32) / 256, 256>>>(t_starts, t_ends, out);
}

// round 3
// speedup vs baseline: 1.0242x; 1.0242x over previous
#include <cuda_runtime.h>
#include <math.h>

#define N_RAYS 32768
#define N_SAMPLES 1048576
#define HID 64
#define TPB 128

// Scratch (device globals; no allocation anywhere)
__device__ float g_sigma_dt[N_SAMPLES];
__device__ float g_rgb[N_SAMPLES * 3];
__device__ int   g_off[N_RAYS + 1];

typedef unsigned long long u64;

__device__ __forceinline__ u64 pack2(float lo, float hi) {
    u64 r;
    asm("mov.b64 %0, {%1, %2};" : "=l"(r) : "f"(lo), "f"(hi));
    return r;
}
__device__ __forceinline__ void unpack2(u64 v, float& lo, float& hi) {
    asm("mov.b64 {%0, %1}, %2;" : "=f"(lo), "=f"(hi) : "l"(v));
}
__device__ __forceinline__ u64 fma2(u64 a, u64 b, u64 c) {
    u64 r;
    asm("fma.rn.f32x2 %0, %1, %2, %3;" : "=l"(r) : "l"(a), "l"(b), "l"(c));
    return r;
}

// ---------------------------------------------------------------------------
// Per-ray segment offsets via boundary scatter (ray_indices is sorted).
// g_off[r] = first sample index with ray_indices >= r; g_off[N_RAYS]=N_SAMPLES.
// ---------------------------------------------------------------------------
__global__ void offsets_kernel(const int* __restrict__ ri) {
    int i = blockIdx.x * 256 + threadIdx.x;
    if (i >= N_SAMPLES) return;
    int cur  = ri[i];
    int prev = (i == 0) ? -1 : ri[i - 1];
    for (int r = prev + 1; r <= cur; r++) g_off[r] = i;
    if (i == N_SAMPLES - 1) {
        for (int r = cur + 1; r <= N_RAYS; r++) g_off[r] = N_SAMPLES;
    }
}

// ---------------------------------------------------------------------------
// MLP kernel: one thread per sample, packed f32x2 FFMA2 inner loops.
// Layer-2 accumulators live as 32 packed pairs (64 fp32). Weights in shared,
// read as broadcast LDS.128 (two packed pairs per load).
// ---------------------------------------------------------------------------
__global__ void __launch_bounds__(TPB) mlp_kernel(
    const float* __restrict__ rays_o, const float* __restrict__ rays_d,
    const float* __restrict__ t_starts, const float* __restrict__ t_ends,
    const int*   __restrict__ ray_indices,
    const float* __restrict__ Wd1, const float* __restrict__ bd1,
    const float* __restrict__ Wd2, const float* __restrict__ bd2,
    const float* __restrict__ Wd3, const float* __restrict__ bd3,
    const float* __restrict__ Wr1, const float* __restrict__ br1,
    const float* __restrict__ Wr2, const float* __restrict__ br2,
    const float* __restrict__ Wr3, const float* __restrict__ br3)
{
    __shared__ float sWd2[HID * HID];
    __shared__ float sWr2[HID * HID];
    __shared__ float sWd1[3 * HID], sWr1[3 * HID], sWr3[HID * 3];
    __shared__ float sWd3[HID];
    __shared__ float sbd1[HID], sbd2[HID], sbr1[HID], sbr2[HID];
    __shared__ float sbd3, sbr3[3];

    const int t = threadIdx.x;
    for (int i = t; i < HID * HID; i += TPB) { sWd2[i] = Wd2[i]; sWr2[i] = Wr2[i]; }
    for (int i = t; i < 3 * HID; i += TPB)  { sWd1[i] = Wd1[i]; sWr1[i] = Wr1[i]; sWr3[i] = Wr3[i]; }
    if (t < HID) { sWd3[t] = Wd3[t]; sbd1[t] = bd1[t]; sbd2[t] = bd2[t]; sbr1[t] = br1[t]; sbr2[t] = br2[t]; }
    if (t == 0) sbd3 = bd3[0];
    if (t < 3)  sbr3[t] = br3[t];
    __syncthreads();

    const int i  = blockIdx.x * TPB + t;
    const int ri = ray_indices[i];
    const float ts  = t_starts[i];
    const float te  = t_ends[i];
    const float mid = 0.5f * (ts + te);
    const float p0 = fmaf(rays_d[ri * 3 + 0], mid, rays_o[ri * 3 + 0]);
    const float p1 = fmaf(rays_d[ri * 3 + 1], mid, rays_o[ri * 3 + 1]);
    const float p2 = fmaf(rays_d[ri * 3 + 2], mid, rays_o[ri * 3 + 2]);

    u64 acc[HID / 2];

    // ======================= density MLP =======================
    {
        const u64* b2 = reinterpret_cast<const u64*>(sbd2);
        #pragma unroll
        for (int j = 0; j < HID / 2; j++) acc[j] = b2[j];
    }
    #pragma unroll 4
    for (int k = 0; k < HID; k++) {
        float hk = sbd1[k];
        hk = fmaf(p0, sWd1[k],           hk);
        hk = fmaf(p1, sWd1[HID + k],     hk);
        hk = fmaf(p2, sWd1[2 * HID + k], hk);
        hk = fmaxf(hk, 0.0f);
        const u64 hk2 = pack2(hk, hk);
        const ulonglong2* wr = reinterpret_cast<const ulonglong2*>(sWd2 + k * HID);
        #pragma unroll
        for (int j = 0; j < HID / 4; j++) {
            ulonglong2 w = wr[j];            // LDS.128 broadcast: 2 packed pairs
            acc[2 * j + 0] = fma2(hk2, w.x, acc[2 * j + 0]);
            acc[2 * j + 1] = fma2(hk2, w.y, acc[2 * j + 1]);
        }
    }
    float sl = sbd3;
    #pragma unroll
    for (int j = 0; j < HID / 2; j++) {
        float a, b; unpack2(acc[j], a, b);
        sl = fmaf(fmaxf(a, 0.0f), sWd3[2 * j + 0], sl);
        sl = fmaf(fmaxf(b, 0.0f), sWd3[2 * j + 1], sl);
    }
    // stable softplus (matches jax.nn.softplus)
    float sigma = fmaxf(sl, 0.0f) + log1pf(expf(-fabsf(sl)));
    g_sigma_dt[i] = sigma * (te - ts);

    // ======================= rgb MLP =======================
    {
        const u64* b2 = reinterpret_cast<const u64*>(sbr2);
        #pragma unroll
        for (int j = 0; j < HID / 2; j++) acc[j] = b2[j];
    }
    #pragma unroll 4
    for (int k = 0; k < HID; k++) {
        float hk = sbr1[k];
        hk = fmaf(p0, sWr1[k],           hk);
        hk = fmaf(p1, sWr1[HID + k],     hk);
        hk = fmaf(p2, sWr1[2 * HID + k], hk);
        hk = fmaxf(hk, 0.0f);
        const u64 hk2 = pack2(hk, hk);
        const ulonglong2* wr = reinterpret_cast<const ulonglong2*>(sWr2 + k * HID);
        #pragma unroll
        for (int j = 0; j < HID / 4; j++) {
            ulonglong2 w = wr[j];
            acc[2 * j + 0] = fma2(hk2, w.x, acc[2 * j + 0]);
            acc[2 * j + 1] = fma2(hk2, w.y, acc[2 * j + 1]);
        }
    }
    float c0 = sbr3[0], c1 = sbr3[1], c2 = sbr3[2];
    #pragma unroll
    for (int j = 0; j < HID / 2; j++) {
        float a, b; unpack2(acc[j], a, b);
        a = fmaxf(a, 0.0f); b = fmaxf(b, 0.0f);
        c0 = fmaf(a, sWr3[(2 * j) * 3 + 0], c0);
        c1 = fmaf(a, sWr3[(2 * j) * 3 + 1], c1);
        c2 = fmaf(a, sWr3[(2 * j) * 3 + 2], c2);
        c0 = fmaf(b, sWr3[(2 * j + 1) * 3 + 0], c0);
        c1 = fmaf(b, sWr3[(2 * j + 1) * 3 + 1], c1);
        c2 = fmaf(b, sWr3[(2 * j + 1) * 3 + 2], c2);
    }
    g_rgb[i * 3 + 0] = 1.0f / (1.0f + expf(-c0));
    g_rgb[i * 3 + 1] = 1.0f / (1.0f + expf(-c1));
    g_rgb[i * 3 + 2] = 1.0f / (1.0f + expf(-c2));
}

// ---------------------------------------------------------------------------
// Render kernel: one warp per ray, segmented exclusive scan via shfl.
// Output layout: [colors (3R) | distances (R) | opacities (R)].
// ---------------------------------------------------------------------------
__global__ void render_kernel(const float* __restrict__ t_starts,
                              const float* __restrict__ t_ends,
                              float* __restrict__ out)
{
    const int gtid = blockIdx.x * blockDim.x + threadIdx.x;
    const int ray  = gtid >> 5;
    const int lane = threadIdx.x & 31;
    if (ray >= N_RAYS) return;

    const int s = g_off[ray];
    const int e = g_off[ray + 1];

    float carry = 0.0f;
    float op = 0.0f, dist = 0.0f;
    float c0 = 0.0f, c1 = 0.0f, c2 = 0.0f;

    for (int base = s; base < e; base += 32) {
        const int  idx = base + lane;
        const bool v   = (idx < e);
        float sd = v ? g_sigma_dt[idx] : 0.0f;

        float x = sd;
        #pragma unroll
        for (int o = 1; o < 32; o <<= 1) {
            float y = __shfl_up_sync(0xffffffffu, x, o);
            if (lane >= o) x += y;
        }
        const float excl = carry + x - sd;
        carry += __shfl_sync(0xffffffffu, x, 31);

        if (v) {
            const float alpha = -expm1f(-sd);
            const float w     = expf(-excl) * alpha;
            const float mid   = 0.5f * (t_starts[idx] + t_ends[idx]);
            op   += w;
            dist += w * mid;
            c0 += w * g_rgb[idx * 3 + 0];
            c1 += w * g_rgb[idx * 3 + 1];
            c2 += w * g_rgb[idx * 3 + 2];
        }
    }

    #pragma unroll
    for (int o = 16; o > 0; o >>= 1) {
        op   += __shfl_down_sync(0xffffffffu, op,   o);
        dist += __shfl_down_sync(0xffffffffu, dist, o);
        c0   += __shfl_down_sync(0xffffffffu, c0,   o);
        c1   += __shfl_down_sync(0xffffffffu, c1,   o);
        c2   += __shfl_down_sync(0xffffffffu, c2,   o);
    }

    if (lane == 0) {
        const float rest = 1.0f - op;
        out[ray * 3 + 0] = c0 + 0.5f * rest;
        out[ray * 3 + 1] = c1 + 0.5f * rest;
        out[ray * 3 + 2] = c2 + 0.5f * rest;
        out[3 * N_RAYS + ray] = dist + 5.0f * rest;
        out[4 * N_RAYS + ray] = op;
    }
}

// ---------------------------------------------------------------------------
extern "C" void kernel_launch(void* const* d_in, const int* in_sizes, int n_in,
                              void* d_out, int out_size)
{
    const float* rays_o      = (const float*)d_in[0];
    const float* rays_d      = (const float*)d_in[1];
    const float* t_starts    = (const float*)d_in[2];
    const float* t_ends      = (const float*)d_in[3];
    const int*   ray_indices = (const int*)  d_in[4];
    const float* W_d1 = (const float*)d_in[5];
    const float* b_d1 = (const float*)d_in[6];
    const float* W_d2 = (const float*)d_in[7];
    const float* b_d2 = (const float*)d_in[8];
    const float* W_d3 = (const float*)d_in[9];
    const float* b_d3 = (const float*)d_in[10];
    const float* W_r1 = (const float*)d_in[11];
    const float* b_r1 = (const float*)d_in[12];
    const float* W_r2 = (const float*)d_in[13];
    const float* b_r2 = (const float*)d_in[14];
    const float* W_r3 = (const float*)d_in[15];
    const float* b_r3 = (const float*)d_in[16];
    float* out = (float*)d_out;

    offsets_kernel<<<N_SAMPLES / 256, 256>>>(ray_indices);

    mlp_kernel<<<N_SAMPLES / TPB, TPB>>>(
        rays_o, rays_d, t_starts, t_ends, ray_indices,
        W_d1, b_d1, W_d2, b_d2, W_d3, b_d3,
        W_r1, b_r1, W_r2, b_r2, W_r3, b_r3);

    render_kernel<<<(N_RAYS * 32) / 256, 256>>>(t_starts, t_ends, out);
}

// round 7
// speedup vs baseline: 2.8722x; 2.8043x over previous
#include <cuda_runtime.h>
#include <cuda_bf16.h>
#include <math.h>
#include <stdint.h>

#define N_RAYS 32768
#define N_SAMPLES 1048576
#define N_TILES (N_SAMPLES / 128)
#define GRID_MLP 296
#define ASTRIDE 144              // 64 bf16 = 128B data + 16B pad (16B-aligned rows, bank-shifted)

// Scratch (device globals; no allocation anywhere)
__device__ float g_sigma_dt[N_SAMPLES];
__device__ float g_rgb[N_SAMPLES * 3];
__device__ int   g_off[N_RAYS + 1];

// ---------------- dynamic SMEM layout (bytes) ----------------
#define A_H    0                 // 128 rows x 144B  activations hi
#define A_L    18432             // activations lo
#define WT_DH  36864             // 64 rows x 144B  W2d^T hi  (Wt[n][k])
#define WT_DL  46080
#define WT_RH  55296
#define WT_RL  64512
#define C_W1D  73728             // 192 f32
#define C_W1R  74496
#define C_B1D  75264             // 64 f32 each
#define C_B1R  75520
#define C_B2D  75776
#define C_B2R  76032
#define C_W3D  76288
#define C_W3R  76544             // 192 f32 col-major [ch*64+n]
#define C_B3   77312             // [0]=bd3, [1..3]=br3
#define C_SDT  77328             // 128 f32 dt per tile row
#define SMEM_TOTAL 77840

// ---------------- PTX helpers ----------------
static __device__ __forceinline__ uint32_t smem_u32(const void* p) {
    uint32_t a;
    asm("{ .reg .u64 t; cvta.to.shared.u64 t, %1; cvt.u32.u64 %0, t; }" : "=r"(a) : "l"(p));
    return a;
}
static __device__ __forceinline__ void ldsm_x4(uint32_t* r, uint32_t addr) {
    asm volatile("ldmatrix.sync.aligned.m8n8.x4.shared.b16 {%0,%1,%2,%3}, [%4];"
                 : "=r"(r[0]), "=r"(r[1]), "=r"(r[2]), "=r"(r[3]) : "r"(addr));
}
static __device__ __forceinline__ void ldsm_x2(uint32_t* r, uint32_t addr) {
    asm volatile("ldmatrix.sync.aligned.m8n8.x2.shared.b16 {%0,%1}, [%2];"
                 : "=r"(r[0]), "=r"(r[1]) : "r"(addr));
}
static __device__ __forceinline__ void mma16816(float* c, const uint32_t* a, const uint32_t* b) {
    asm volatile("mma.sync.aligned.m16n8k16.row.col.f32.bf16.bf16.f32 "
                 "{%0,%1,%2,%3}, {%4,%5,%6,%7}, {%8,%9}, {%0,%1,%2,%3};"
                 : "+f"(c[0]), "+f"(c[1]), "+f"(c[2]), "+f"(c[3])
                 : "r"(a[0]), "r"(a[1]), "r"(a[2]), "r"(a[3]), "r"(b[0]), "r"(b[1]));
}

// ---------------------------------------------------------------------------
// Layer-1 (3 -> 64) scalar + bf16 hi/lo split; store one A row (stride 144B).
// ---------------------------------------------------------------------------
static __device__ __forceinline__ void l1_store(char* smem, int w1off, int b1off,
                                                int t, float p0, float p1, float p2)
{
    const float4* W0 = (const float4*)(smem + w1off);
    const float4* W1 = (const float4*)(smem + w1off + 256);
    const float4* W2 = (const float4*)(smem + w1off + 512);
    const float4* B  = (const float4*)(smem + b1off);
    char* rowH = smem + A_H + t * ASTRIDE;
    char* rowL = smem + A_L + t * ASTRIDE;
    #pragma unroll
    for (int g = 0; g < 8; g++) {
        uint32_t hi[4], lo[4];
        #pragma unroll
        for (int q = 0; q < 2; q++) {
            int j = g * 2 + q;
            float4 w0 = W0[j], w1 = W1[j], w2 = W2[j], b = B[j];
            float h0 = fmaxf(fmaf(p2, w2.x, fmaf(p1, w1.x, fmaf(p0, w0.x, b.x))), 0.0f);
            float h1 = fmaxf(fmaf(p2, w2.y, fmaf(p1, w1.y, fmaf(p0, w0.y, b.y))), 0.0f);
            float h2 = fmaxf(fmaf(p2, w2.z, fmaf(p1, w1.z, fmaf(p0, w0.z, b.z))), 0.0f);
            float h3 = fmaxf(fmaf(p2, w2.w, fmaf(p1, w1.w, fmaf(p0, w0.w, b.w))), 0.0f);
            __nv_bfloat16 H0 = __float2bfloat16_rn(h0), H1 = __float2bfloat16_rn(h1);
            __nv_bfloat16 H2 = __float2bfloat16_rn(h2), H3 = __float2bfloat16_rn(h3);
            hi[2*q+0] = (uint32_t)__bfloat16_as_ushort(H0) | ((uint32_t)__bfloat16_as_ushort(H1) << 16);
            hi[2*q+1] = (uint32_t)__bfloat16_as_ushort(H2) | ((uint32_t)__bfloat16_as_ushort(H3) << 16);
            __nv_bfloat16 L0 = __float2bfloat16_rn(h0 - __bfloat162float(H0));
            __nv_bfloat16 L1 = __float2bfloat16_rn(h1 - __bfloat162float(H1));
            __nv_bfloat16 L2 = __float2bfloat16_rn(h2 - __bfloat162float(H2));
            __nv_bfloat16 L3 = __float2bfloat16_rn(h3 - __bfloat162float(H3));
            lo[2*q+0] = (uint32_t)__bfloat16_as_ushort(L0) | ((uint32_t)__bfloat16_as_ushort(L1) << 16);
            lo[2*q+1] = (uint32_t)__bfloat16_as_ushort(L2) | ((uint32_t)__bfloat16_as_ushort(L3) << 16);
        }
        *(uint4*)(rowH + g * 16) = make_uint4(hi[0], hi[1], hi[2], hi[3]);
        *(uint4*)(rowL + g * 16) = make_uint4(lo[0], lo[1], lo[2], lo[3]);
    }
}

// ---------------------------------------------------------------------------
// Layer-2 via mma.sync: warp computes its 32 rows x 64 cols, K=64.
// 3 split terms: Ah*Wh + Al*Wh + Ah*Wl. acc zero-initialized here.
// ---------------------------------------------------------------------------
static __device__ __forceinline__ void run_net(
    uint32_t sb, int bHoff, int bLoff, int m0,
    uint32_t aoff, uint32_t boff, float acc[2][8][4])
{
    #pragma unroll
    for (int mb = 0; mb < 2; mb++)
        #pragma unroll
        for (int n = 0; n < 8; n++)
            #pragma unroll
            for (int e = 0; e < 4; e++) acc[mb][n][e] = 0.0f;

    #pragma unroll
    for (int k = 0; k < 4; k++) {
        uint32_t ah0[4], al0[4], ah1[4], al1[4];
        const uint32_t aH = sb + A_H + (uint32_t)(m0 * ASTRIDE) + k * 32 + aoff;
        const uint32_t aL = sb + A_L + (uint32_t)(m0 * ASTRIDE) + k * 32 + aoff;
        ldsm_x4(ah0, aH);
        ldsm_x4(ah1, aH + 16 * ASTRIDE);
        ldsm_x4(al0, aL);
        ldsm_x4(al1, aL + 16 * ASTRIDE);
        #pragma unroll
        for (int n = 0; n < 8; n++) {
            uint32_t bh[2], bl[2];
            ldsm_x2(bh, sb + bHoff + n * 8 * ASTRIDE + k * 32 + boff);
            ldsm_x2(bl, sb + bLoff + n * 8 * ASTRIDE + k * 32 + boff);
            mma16816(acc[0][n], ah0, bh);
            mma16816(acc[0][n], al0, bh);
            mma16816(acc[0][n], ah0, bl);
            mma16816(acc[1][n], ah1, bh);
            mma16816(acc[1][n], al1, bh);
            mma16816(acc[1][n], ah1, bl);
        }
    }
}

// ---------------------------------------------------------------------------
// Fused MLP kernel: persistent CTAs, 128-sample tiles, warp-synchronous.
// ---------------------------------------------------------------------------
__global__ void __launch_bounds__(128) mlp_tc_kernel(
    const float* __restrict__ rays_o, const float* __restrict__ rays_d,
    const float* __restrict__ t_starts, const float* __restrict__ t_ends,
    const int*   __restrict__ ray_indices,
    const float* __restrict__ Wd1, const float* __restrict__ bd1,
    const float* __restrict__ Wd2, const float* __restrict__ bd2,
    const float* __restrict__ Wd3, const float* __restrict__ bd3,
    const float* __restrict__ Wr1, const float* __restrict__ br1,
    const float* __restrict__ Wr2, const float* __restrict__ br2,
    const float* __restrict__ Wr3, const float* __restrict__ br3)
{
    extern __shared__ char smem[];
    const uint32_t sb = smem_u32(smem);
    const int t    = threadIdx.x;
    const int lane = t & 31;
    const int wid  = t >> 5;
    const int m0   = wid * 32;

    // -------- one-time weight prep --------
    {
        float* w1d = (float*)(smem + C_W1D);
        float* w1r = (float*)(smem + C_W1R);
        float* w3r = (float*)(smem + C_W3R);
        for (int i = t; i < 192; i += 128) {
            w1d[i] = Wd1[i]; w1r[i] = Wr1[i];
            w3r[(i % 3) * 64 + (i / 3)] = Wr3[i];     // col-major [ch*64+n]
        }
        if (t < 64) {
            ((float*)(smem + C_B1D))[t] = bd1[t];
            ((float*)(smem + C_B1R))[t] = br1[t];
            ((float*)(smem + C_B2D))[t] = bd2[t];
            ((float*)(smem + C_B2R))[t] = br2[t];
            ((float*)(smem + C_W3D))[t] = Wd3[t];
        }
        if (t == 0) ((float*)(smem + C_B3))[0] = bd3[0];
        if (t < 3)  ((float*)(smem + C_B3))[1 + t] = br3[t];
        // W2 -> Wt[n][k] = W2[k][n], bf16 hi/lo, stride 144B
        for (int idx = t; idx < 4096; idx += 128) {
            int k = idx >> 6, n = idx & 63;
            int off = n * ASTRIDE + k * 2;
            float wd = Wd2[idx], wr = Wr2[idx];
            __nv_bfloat16 hd = __float2bfloat16_rn(wd);
            __nv_bfloat16 hr = __float2bfloat16_rn(wr);
            *(__nv_bfloat16*)(smem + WT_DH + off) = hd;
            *(__nv_bfloat16*)(smem + WT_DL + off) = __float2bfloat16_rn(wd - __bfloat162float(hd));
            *(__nv_bfloat16*)(smem + WT_RH + off) = hr;
            *(__nv_bfloat16*)(smem + WT_RL + off) = __float2bfloat16_rn(wr - __bfloat162float(hr));
        }
    }
    __syncthreads();

    // per-lane ldmatrix offsets
    const uint32_t aoff = (uint32_t)(((lane & 7) + ((lane >> 3) & 1) * 8) * ASTRIDE
                                     + ((lane >> 4) & 1) * 16);
    const int l16 = lane & 15;
    const uint32_t boff = (uint32_t)((l16 & 7) * ASTRIDE + ((l16 >> 3) & 1) * 16);

    const float* b2d = (const float*)(smem + C_B2D);
    const float* b2r = (const float*)(smem + C_B2R);
    const float* w3d = (const float*)(smem + C_W3D);
    const float* w3r = (const float*)(smem + C_W3R);
    const float* bb3 = (const float*)(smem + C_B3);
    float* sdt = (float*)(smem + C_SDT);

    const int j   = lane & 3;
    const int row = m0 + (lane >> 2) + 8 * j;   // output row this thread owns

    for (int tile = blockIdx.x; tile < N_TILES; tile += gridDim.x) {
        const int s  = tile * 128 + t;
        const int ri = ray_indices[s];
        const float ts_ = t_starts[s], te_ = t_ends[s];
        const float mid = 0.5f * (ts_ + te_);
        const float p0 = fmaf(rays_d[ri * 3 + 0], mid, rays_o[ri * 3 + 0]);
        const float p1 = fmaf(rays_d[ri * 3 + 1], mid, rays_o[ri * 3 + 1]);
        const float p2 = fmaf(rays_d[ri * 3 + 2], mid, rays_o[ri * 3 + 2]);
        sdt[t] = te_ - ts_;

        // ================= density net =================
        l1_store(smem, C_W1D, C_B1D, t, p0, p1, p2);
        __syncwarp();
        {
            float acc[2][8][4];
            run_net(sb, WT_DH, WT_DL, m0, aoff, boff, acc);
            float s0 = 0.f, s1 = 0.f, s2 = 0.f, s3 = 0.f;
            #pragma unroll
            for (int n = 0; n < 8; n++) {
                const int cA = n * 8 + 2 * j;
                const float ba = b2d[cA], bb = b2d[cA + 1];
                const float wa = w3d[cA], wb = w3d[cA + 1];
                s0 = fmaf(fmaxf(acc[0][n][0] + ba, 0.f), wa, fmaf(fmaxf(acc[0][n][1] + bb, 0.f), wb, s0));
                s1 = fmaf(fmaxf(acc[0][n][2] + ba, 0.f), wa, fmaf(fmaxf(acc[0][n][3] + bb, 0.f), wb, s1));
                s2 = fmaf(fmaxf(acc[1][n][0] + ba, 0.f), wa, fmaf(fmaxf(acc[1][n][1] + bb, 0.f), wb, s2));
                s3 = fmaf(fmaxf(acc[1][n][2] + ba, 0.f), wa, fmaf(fmaxf(acc[1][n][3] + bb, 0.f), wb, s3));
            }
            s0 += __shfl_xor_sync(0xffffffffu, s0, 1); s0 += __shfl_xor_sync(0xffffffffu, s0, 2);
            s1 += __shfl_xor_sync(0xffffffffu, s1, 1); s1 += __shfl_xor_sync(0xffffffffu, s1, 2);
            s2 += __shfl_xor_sync(0xffffffffu, s2, 1); s2 += __shfl_xor_sync(0xffffffffu, s2, 2);
            s3 += __shfl_xor_sync(0xffffffffu, s3, 1); s3 += __shfl_xor_sync(0xffffffffu, s3, 2);
            const float sl = ((j == 0) ? s0 : (j == 1) ? s1 : (j == 2) ? s2 : s3) + bb3[0];
            const float sigma = fmaxf(sl, 0.0f) + log1pf(expf(-fabsf(sl)));
            g_sigma_dt[tile * 128 + row] = sigma * sdt[row];
        }
        __syncwarp();

        // ================= rgb net =================
        l1_store(smem, C_W1R, C_B1R, t, p0, p1, p2);
        __syncwarp();
        {
            float acc[2][8][4];
            run_net(sb, WT_RH, WT_RL, m0, aoff, boff, acc);
            float rr[4][3];
            #pragma unroll
            for (int q = 0; q < 4; q++) { rr[q][0] = 0.f; rr[q][1] = 0.f; rr[q][2] = 0.f; }
            #pragma unroll
            for (int n = 0; n < 8; n++) {
                const int cA = n * 8 + 2 * j;
                const float ba = b2r[cA], bb = b2r[cA + 1];
                const float wa0 = w3r[cA],        wb0 = w3r[cA + 1];
                const float wa1 = w3r[64 + cA],   wb1 = w3r[64 + cA + 1];
                const float wa2 = w3r[128 + cA],  wb2 = w3r[128 + cA + 1];
                #pragma unroll
                for (int mb = 0; mb < 2; mb++) {
                    const float hA0 = fmaxf(acc[mb][n][0] + ba, 0.f);
                    const float hB0 = fmaxf(acc[mb][n][1] + bb, 0.f);
                    const float hA1 = fmaxf(acc[mb][n][2] + ba, 0.f);
                    const float hB1 = fmaxf(acc[mb][n][3] + bb, 0.f);
                    rr[mb*2+0][0] = fmaf(hA0, wa0, fmaf(hB0, wb0, rr[mb*2+0][0]));
                    rr[mb*2+0][1] = fmaf(hA0, wa1, fmaf(hB0, wb1, rr[mb*2+0][1]));
                    rr[mb*2+0][2] = fmaf(hA0, wa2, fmaf(hB0, wb2, rr[mb*2+0][2]));
                    rr[mb*2+1][0] = fmaf(hA1, wa0, fmaf(hB1, wb0, rr[mb*2+1][0]));
                    rr[mb*2+1][1] = fmaf(hA1, wa1, fmaf(hB1, wb1, rr[mb*2+1][1]));
                    rr[mb*2+1][2] = fmaf(hA1, wa2, fmaf(hB1, wb2, rr[mb*2+1][2]));
                }
            }
            #pragma unroll
            for (int q = 0; q < 4; q++)
                #pragma unroll
                for (int ch = 0; ch < 3; ch++) {
                    rr[q][ch] += __shfl_xor_sync(0xffffffffu, rr[q][ch], 1);
                    rr[q][ch] += __shfl_xor_sync(0xffffffffu, rr[q][ch], 2);
                }
            const float c0 = ((j==0)?rr[0][0]:(j==1)?rr[1][0]:(j==2)?rr[2][0]:rr[3][0]) + bb3[1];
            const float c1 = ((j==0)?rr[0][1]:(j==1)?rr[1][1]:(j==2)?rr[2][1]:rr[3][1]) + bb3[2];
            const float c2 = ((j==0)?rr[0][2]:(j==1)?rr[1][2]:(j==2)?rr[2][2]:rr[3][2]) + bb3[3];
            const int so = (tile * 128 + row) * 3;
            g_rgb[so + 0] = 1.0f / (1.0f + expf(-c0));
            g_rgb[so + 1] = 1.0f / (1.0f + expf(-c1));
            g_rgb[so + 2] = 1.0f / (1.0f + expf(-c2));
        }
        __syncwarp();
    }
}

// ---------------------------------------------------------------------------
// Per-ray segment offsets via boundary scatter (ray_indices is sorted).
// ---------------------------------------------------------------------------
__global__ void offsets_kernel(const int* __restrict__ ri) {
    int i = blockIdx.x * 256 + threadIdx.x;
    if (i >= N_SAMPLES) return;
    int cur  = ri[i];
    int prev = (i == 0) ? -1 : ri[i - 1];
    for (int r = prev + 1; r <= cur; r++) g_off[r] = i;
    if (i == N_SAMPLES - 1) {
        for (int r = cur + 1; r <= N_RAYS; r++) g_off[r] = N_SAMPLES;
    }
}

// ---------------------------------------------------------------------------
// Render kernel: one warp per ray, segmented exclusive scan via shfl.
// Output layout: [colors (3R) | distances (R) | opacities (R)].
// ---------------------------------------------------------------------------
__global__ void render_kernel(const float* __restrict__ t_starts,
                              const float* __restrict__ t_ends,
                              float* __restrict__ out)
{
    const int gtid = blockIdx.x * blockDim.x + threadIdx.x;
    const int ray  = gtid >> 5;
    const int lane = threadIdx.x & 31;
    if (ray >= N_RAYS) return;

    const int s = g_off[ray];
    const int e = g_off[ray + 1];

    float carry = 0.0f;
    float op = 0.0f, dist = 0.0f;
    float c0 = 0.0f, c1 = 0.0f, c2 = 0.0f;

    for (int base = s; base < e; base += 32) {
        const int  idx = base + lane;
        const bool v   = (idx < e);
        float sd = v ? g_sigma_dt[idx] : 0.0f;

        float x = sd;
        #pragma unroll
        for (int o = 1; o < 32; o <<= 1) {
            float y = __shfl_up_sync(0xffffffffu, x, o);
            if (lane >= o) x += y;
        }
        const float excl = carry + x - sd;
        carry += __shfl_sync(0xffffffffu, x, 31);

        if (v) {
            const float alpha = -expm1f(-sd);
            const float w     = expf(-excl) * alpha;
            const float m     = 0.5f * (t_starts[idx] + t_ends[idx]);
            op   += w;
            dist += w * m;
            c0 += w * g_rgb[idx * 3 + 0];
            c1 += w * g_rgb[idx * 3 + 1];
            c2 += w * g_rgb[idx * 3 + 2];
        }
    }

    #pragma unroll
    for (int o = 16; o > 0; o >>= 1) {
        op   += __shfl_down_sync(0xffffffffu, op,   o);
        dist += __shfl_down_sync(0xffffffffu, dist, o);
        c0   += __shfl_down_sync(0xffffffffu, c0,   o);
        c1   += __shfl_down_sync(0xffffffffu, c1,   o);
        c2   += __shfl_down_sync(0xffffffffu, c2,   o);
    }

    if (lane == 0) {
        const float rest = 1.0f - op;
        out[ray * 3 + 0] = c0 + 0.5f * rest;
        out[ray * 3 + 1] = c1 + 0.5f * rest;
        out[ray * 3 + 2] = c2 + 0.5f * rest;
        out[3 * N_RAYS + ray] = dist + 5.0f * rest;
        out[4 * N_RAYS + ray] = op;
    }
}

// ---------------------------------------------------------------------------
extern "C" void kernel_launch(void* const* d_in, const int* in_sizes, int n_in,
                              void* d_out, int out_size)
{
    const float* rays_o      = (const float*)d_in[0];
    const float* rays_d      = (const float*)d_in[1];
    const float* t_starts    = (const float*)d_in[2];
    const float* t_ends      = (const float*)d_in[3];
    const int*   ray_indices = (const int*)  d_in[4];
    const float* W_d1 = (const float*)d_in[5];
    const float* b_d1 = (const float*)d_in[6];
    const float* W_d2 = (const float*)d_in[7];
    const float* b_d2 = (const float*)d_in[8];
    const float* W_d3 = (const float*)d_in[9];
    const float* b_d3 = (const float*)d_in[10];
    const float* W_r1 = (const float*)d_in[11];
    const float* b_r1 = (const float*)d_in[12];
    const float* W_r2 = (const float*)d_in[13];
    const float* b_r2 = (const float*)d_in[14];
    const float* W_r3 = (const float*)d_in[15];
    const float* b_r3 = (const float*)d_in[16];
    float* out = (float*)d_out;

    cudaFuncSetAttribute((const void*)mlp_tc_kernel,
                         cudaFuncAttributeMaxDynamicSharedMemorySize, SMEM_TOTAL);

    offsets_kernel<<<N_SAMPLES / 256, 256>>>(ray_indices);

    mlp_tc_kernel<<<GRID_MLP, 128, SMEM_TOTAL>>>(
        rays_o, rays_d, t_starts, t_ends, ray_indices,
        W_d1, b_d1, W_d2, b_d2, W_d3, b_d3,
        W_r1, b_r1, W_r2, b_r2, W_r3, b_r3);

    render_kernel<<<(N_RAYS * 32) / 256, 256>>>(t_starts, t_ends, out);
}

// round 8
// speedup vs baseline: 3.8065x; 1.3253x over previous
#include <cuda_runtime.h>
#include <cuda_fp16.h>
#include <math.h>
#include <stdint.h>

#define N_RAYS 32768
#define N_SAMPLES 1048576
#define N_TILES (N_SAMPLES / 128)
#define GRID_MLP 444
#define ASTRIDE 144              // 64 fp16 = 128B data + 16B pad (16B-aligned rows, 4-bank shift)

// Scratch (device globals; no allocation anywhere)
__device__ float g_sigma_dt[N_SAMPLES];
__device__ float g_rgb[N_SAMPLES * 3];
__device__ int   g_off[N_RAYS + 1];

// ---------------- dynamic SMEM layout (bytes) ----------------
#define A_H    0                 // 128 rows x 144B  activations hi
#define A_L    18432             // activations lo
#define WT_DH  36864             // 64 rows x 144B  W2d^T fp16  (Wt[n][k])
#define WT_RH  46080             // W2r^T fp16
#define C_W1D  55296             // 192 f32
#define C_W1R  56064
#define C_B1D  56832             // 64 f32 each
#define C_B1R  57088
#define C_B2D  57344
#define C_B2R  57600
#define C_W3D  57856
#define C_W3R  58112             // 192 f32 col-major [ch*64+n]
#define C_B3   58880             // [0]=bd3, [1..3]=br3
#define C_SDT  58896             // 128 f32 dt per tile row
#define SMEM_TOTAL 59424

// ---------------- PTX helpers ----------------
static __device__ __forceinline__ uint32_t smem_u32(const void* p) {
    uint32_t a;
    asm("{ .reg .u64 t; cvta.to.shared.u64 t, %1; cvt.u32.u64 %0, t; }" : "=r"(a) : "l"(p));
    return a;
}
static __device__ __forceinline__ void ldsm_x4(uint32_t* r, uint32_t addr) {
    asm volatile("ldmatrix.sync.aligned.m8n8.x4.shared.b16 {%0,%1,%2,%3}, [%4];"
                 : "=r"(r[0]), "=r"(r[1]), "=r"(r[2]), "=r"(r[3]) : "r"(addr));
}
static __device__ __forceinline__ void ldsm_x2(uint32_t* r, uint32_t addr) {
    asm volatile("ldmatrix.sync.aligned.m8n8.x2.shared.b16 {%0,%1}, [%2];"
                 : "=r"(r[0]), "=r"(r[1]) : "r"(addr));
}
static __device__ __forceinline__ void mma16816(float* c, const uint32_t* a, const uint32_t* b) {
    asm volatile("mma.sync.aligned.m16n8k16.row.col.f32.f16.f16.f32 "
                 "{%0,%1,%2,%3}, {%4,%5,%6,%7}, {%8,%9}, {%0,%1,%2,%3};"
                 : "+f"(c[0]), "+f"(c[1]), "+f"(c[2]), "+f"(c[3])
                 : "r"(a[0]), "r"(a[1]), "r"(a[2]), "r"(a[3]), "r"(b[0]), "r"(b[1]));
}
static __device__ __forceinline__ uint32_t h2_u32(__half2 h) {
    return *reinterpret_cast<uint32_t*>(&h);
}

// ---------------------------------------------------------------------------
// Layer-1 (3 -> 64) scalar + fp16 hi/lo split; store one A row (stride 144B).
// ---------------------------------------------------------------------------
static __device__ __forceinline__ void l1_store(char* smem, int w1off, int b1off,
                                                int t, float p0, float p1, float p2)
{
    const float4* W0 = (const float4*)(smem + w1off);
    const float4* W1 = (const float4*)(smem + w1off + 256);
    const float4* W2 = (const float4*)(smem + w1off + 512);
    const float4* B  = (const float4*)(smem + b1off);
    char* rowH = smem + A_H + t * ASTRIDE;
    char* rowL = smem + A_L + t * ASTRIDE;
    #pragma unroll
    for (int g = 0; g < 8; g++) {
        uint32_t hi[4], lo[4];
        #pragma unroll
        for (int q = 0; q < 2; q++) {
            int j = g * 2 + q;
            float4 w0 = W0[j], w1 = W1[j], w2 = W2[j], b = B[j];
            float h0 = fmaxf(fmaf(p2, w2.x, fmaf(p1, w1.x, fmaf(p0, w0.x, b.x))), 0.0f);
            float h1 = fmaxf(fmaf(p2, w2.y, fmaf(p1, w1.y, fmaf(p0, w0.y, b.y))), 0.0f);
            float h2 = fmaxf(fmaf(p2, w2.z, fmaf(p1, w1.z, fmaf(p0, w0.z, b.z))), 0.0f);
            float h3 = fmaxf(fmaf(p2, w2.w, fmaf(p1, w1.w, fmaf(p0, w0.w, b.w))), 0.0f);
            __half2 H01 = __floats2half2_rn(h0, h1);
            __half2 H23 = __floats2half2_rn(h2, h3);
            float2 f01 = __half22float2(H01);
            float2 f23 = __half22float2(H23);
            __half2 L01 = __floats2half2_rn(h0 - f01.x, h1 - f01.y);
            __half2 L23 = __floats2half2_rn(h2 - f23.x, h3 - f23.y);
            hi[2*q+0] = h2_u32(H01);
            hi[2*q+1] = h2_u32(H23);
            lo[2*q+0] = h2_u32(L01);
            lo[2*q+1] = h2_u32(L23);
        }
        *(uint4*)(rowH + g * 16) = make_uint4(hi[0], hi[1], hi[2], hi[3]);
        *(uint4*)(rowL + g * 16) = make_uint4(lo[0], lo[1], lo[2], lo[3]);
    }
}

// ---------------------------------------------------------------------------
// Layer-2 via mma.sync: warp computes its 32 rows x 64 cols, K=64.
// 2 split terms: Ah*Wh + Al*Wh (W single fp16). acc zero-initialized here.
// ---------------------------------------------------------------------------
static __device__ __forceinline__ void run_net(
    uint32_t sb, int bHoff, int m0,
    uint32_t aoff, uint32_t boff, float acc[2][8][4])
{
    #pragma unroll
    for (int mb = 0; mb < 2; mb++)
        #pragma unroll
        for (int n = 0; n < 8; n++)
            #pragma unroll
            for (int e = 0; e < 4; e++) acc[mb][n][e] = 0.0f;

    #pragma unroll
    for (int k = 0; k < 4; k++) {
        uint32_t ah0[4], al0[4], ah1[4], al1[4];
        const uint32_t aH = sb + A_H + (uint32_t)(m0 * ASTRIDE) + k * 32 + aoff;
        const uint32_t aL = sb + A_L + (uint32_t)(m0 * ASTRIDE) + k * 32 + aoff;
        ldsm_x4(ah0, aH);
        ldsm_x4(ah1, aH + 16 * ASTRIDE);
        ldsm_x4(al0, aL);
        ldsm_x4(al1, aL + 16 * ASTRIDE);
        #pragma unroll
        for (int n = 0; n < 8; n++) {
            uint32_t bh[2];
            ldsm_x2(bh, sb + bHoff + n * 8 * ASTRIDE + k * 32 + boff);
            mma16816(acc[0][n], ah0, bh);
            mma16816(acc[0][n], al0, bh);
            mma16816(acc[1][n], ah1, bh);
            mma16816(acc[1][n], al1, bh);
        }
    }
}

// ---------------------------------------------------------------------------
// Fused MLP kernel: persistent CTAs, 128-sample tiles, warp-synchronous.
// Also scatters per-ray segment offsets (ray_indices sorted) on the fly.
// ---------------------------------------------------------------------------
__global__ void __launch_bounds__(128) mlp_tc_kernel(
    const float* __restrict__ rays_o, const float* __restrict__ rays_d,
    const float* __restrict__ t_starts, const float* __restrict__ t_ends,
    const int*   __restrict__ ray_indices,
    const float* __restrict__ Wd1, const float* __restrict__ bd1,
    const float* __restrict__ Wd2, const float* __restrict__ bd2,
    const float* __restrict__ Wd3, const float* __restrict__ bd3,
    const float* __restrict__ Wr1, const float* __restrict__ br1,
    const float* __restrict__ Wr2, const float* __restrict__ br2,
    const float* __restrict__ Wr3, const float* __restrict__ br3)
{
    extern __shared__ char smem[];
    const uint32_t sb = smem_u32(smem);
    const int t    = threadIdx.x;
    const int lane = t & 31;
    const int wid  = t >> 5;
    const int m0   = wid * 32;

    // -------- one-time weight prep --------
    {
        float* w1d = (float*)(smem + C_W1D);
        float* w1r = (float*)(smem + C_W1R);
        float* w3r = (float*)(smem + C_W3R);
        for (int i = t; i < 192; i += 128) {
            w1d[i] = Wd1[i]; w1r[i] = Wr1[i];
            w3r[(i % 3) * 64 + (i / 3)] = Wr3[i];     // col-major [ch*64+n]
        }
        if (t < 64) {
            ((float*)(smem + C_B1D))[t] = bd1[t];
            ((float*)(smem + C_B1R))[t] = br1[t];
            ((float*)(smem + C_B2D))[t] = bd2[t];
            ((float*)(smem + C_B2R))[t] = br2[t];
            ((float*)(smem + C_W3D))[t] = Wd3[t];
        }
        if (t == 0) ((float*)(smem + C_B3))[0] = bd3[0];
        if (t < 3)  ((float*)(smem + C_B3))[1 + t] = br3[t];
        // W2 -> Wt[n][k] = W2[k][n], single fp16, stride 144B
        for (int idx = t; idx < 4096; idx += 128) {
            int k = idx >> 6, n = idx & 63;
            int off = n * ASTRIDE + k * 2;
            *(__half*)(smem + WT_DH + off) = __float2half_rn(Wd2[idx]);
            *(__half*)(smem + WT_RH + off) = __float2half_rn(Wr2[idx]);
        }
    }
    __syncthreads();

    // per-lane ldmatrix offsets
    const uint32_t aoff = (uint32_t)(((lane & 7) + ((lane >> 3) & 1) * 8) * ASTRIDE
                                     + ((lane >> 4) & 1) * 16);
    const int l16 = lane & 15;
    const uint32_t boff = (uint32_t)((l16 & 7) * ASTRIDE + ((l16 >> 3) & 1) * 16);

    const float* b2d = (const float*)(smem + C_B2D);
    const float* b2r = (const float*)(smem + C_B2R);
    const float* w3d = (const float*)(smem + C_W3D);
    const float* w3r = (const float*)(smem + C_W3R);
    const float* bb3 = (const float*)(smem + C_B3);
    float* sdt = (float*)(smem + C_SDT);

    const int j   = lane & 3;
    const int row = m0 + (lane >> 2) + 8 * j;   // output row this thread owns

    for (int tile = blockIdx.x; tile < N_TILES; tile += gridDim.x) {
        const int s  = tile * 128 + t;
        const int ri = ray_indices[s];

        // fused per-ray offset scatter (ray_indices sorted)
        {
            const int prev = (s == 0) ? -1 : ray_indices[s - 1];
            for (int r = prev + 1; r <= ri; r++) g_off[r] = s;
            if (s == N_SAMPLES - 1)
                for (int r = ri + 1; r <= N_RAYS; r++) g_off[r] = N_SAMPLES;
        }

        const float ts_ = t_starts[s], te_ = t_ends[s];
        const float mid = 0.5f * (ts_ + te_);
        const float p0 = fmaf(rays_d[ri * 3 + 0], mid, rays_o[ri * 3 + 0]);
        const float p1 = fmaf(rays_d[ri * 3 + 1], mid, rays_o[ri * 3 + 1]);
        const float p2 = fmaf(rays_d[ri * 3 + 2], mid, rays_o[ri * 3 + 2]);
        sdt[t] = te_ - ts_;

        // ================= density net =================
        l1_store(smem, C_W1D, C_B1D, t, p0, p1, p2);
        __syncwarp();
        {
            float acc[2][8][4];
            run_net(sb, WT_DH, m0, aoff, boff, acc);
            float s0 = 0.f, s1 = 0.f, s2 = 0.f, s3 = 0.f;
            #pragma unroll
            for (int n = 0; n < 8; n++) {
                const int cA = n * 8 + 2 * j;
                const float ba = b2d[cA], bb = b2d[cA + 1];
                const float wa = w3d[cA], wb = w3d[cA + 1];
                s0 = fmaf(fmaxf(acc[0][n][0] + ba, 0.f), wa, fmaf(fmaxf(acc[0][n][1] + bb, 0.f), wb, s0));
                s1 = fmaf(fmaxf(acc[0][n][2] + ba, 0.f), wa, fmaf(fmaxf(acc[0][n][3] + bb, 0.f), wb, s1));
                s2 = fmaf(fmaxf(acc[1][n][0] + ba, 0.f), wa, fmaf(fmaxf(acc[1][n][1] + bb, 0.f), wb, s2));
                s3 = fmaf(fmaxf(acc[1][n][2] + ba, 0.f), wa, fmaf(fmaxf(acc[1][n][3] + bb, 0.f), wb, s3));
            }
            s0 += __shfl_xor_sync(0xffffffffu, s0, 1); s0 += __shfl_xor_sync(0xffffffffu, s0, 2);
            s1 += __shfl_xor_sync(0xffffffffu, s1, 1); s1 += __shfl_xor_sync(0xffffffffu, s1, 2);
            s2 += __shfl_xor_sync(0xffffffffu, s2, 1); s2 += __shfl_xor_sync(0xffffffffu, s2, 2);
            s3 += __shfl_xor_sync(0xffffffffu, s3, 1); s3 += __shfl_xor_sync(0xffffffffu, s3, 2);
            const float sl = ((j == 0) ? s0 : (j == 1) ? s1 : (j == 2) ? s2 : s3) + bb3[0];
            const float sigma = fmaxf(sl, 0.0f) + log1pf(expf(-fabsf(sl)));
            g_sigma_dt[tile * 128 + row] = sigma * sdt[row];
        }
        __syncwarp();

        // ================= rgb net =================
        l1_store(smem, C_W1R, C_B1R, t, p0, p1, p2);
        __syncwarp();
        {
            float acc[2][8][4];
            run_net(sb, WT_RH, m0, aoff, boff, acc);
            float rr[4][3];
            #pragma unroll
            for (int q = 0; q < 4; q++) { rr[q][0] = 0.f; rr[q][1] = 0.f; rr[q][2] = 0.f; }
            #pragma unroll
            for (int n = 0; n < 8; n++) {
                const int cA = n * 8 + 2 * j;
                const float ba = b2r[cA], bb = b2r[cA + 1];
                const float wa0 = w3r[cA],        wb0 = w3r[cA + 1];
                const float wa1 = w3r[64 + cA],   wb1 = w3r[64 + cA + 1];
                const float wa2 = w3r[128 + cA],  wb2 = w3r[128 + cA + 1];
                #pragma unroll
                for (int mb = 0; mb < 2; mb++) {
                    const float hA0 = fmaxf(acc[mb][n][0] + ba, 0.f);
                    const float hB0 = fmaxf(acc[mb][n][1] + bb, 0.f);
                    const float hA1 = fmaxf(acc[mb][n][2] + ba, 0.f);
                    const float hB1 = fmaxf(acc[mb][n][3] + bb, 0.f);
                    rr[mb*2+0][0] = fmaf(hA0, wa0, fmaf(hB0, wb0, rr[mb*2+0][0]));
                    rr[mb*2+0][1] = fmaf(hA0, wa1, fmaf(hB0, wb1, rr[mb*2+0][1]));
                    rr[mb*2+0][2] = fmaf(hA0, wa2, fmaf(hB0, wb2, rr[mb*2+0][2]));
                    rr[mb*2+1][0] = fmaf(hA1, wa0, fmaf(hB1, wb0, rr[mb*2+1][0]));
                    rr[mb*2+1][1] = fmaf(hA1, wa1, fmaf(hB1, wb1, rr[mb*2+1][1]));
                    rr[mb*2+1][2] = fmaf(hA1, wa2, fmaf(hB1, wb2, rr[mb*2+1][2]));
                }
            }
            #pragma unroll
            for (int q = 0; q < 4; q++)
                #pragma unroll
                for (int ch = 0; ch < 3; ch++) {
                    rr[q][ch] += __shfl_xor_sync(0xffffffffu, rr[q][ch], 1);
                    rr[q][ch] += __shfl_xor_sync(0xffffffffu, rr[q][ch], 2);
                }
            const float c0 = ((j==0)?rr[0][0]:(j==1)?rr[1][0]:(j==2)?rr[2][0]:rr[3][0]) + bb3[1];
            const float c1 = ((j==0)?rr[0][1]:(j==1)?rr[1][1]:(j==2)?rr[2][1]:rr[3][1]) + bb3[2];
            const float c2 = ((j==0)?rr[0][2]:(j==1)?rr[1][2]:(j==2)?rr[2][2]:rr[3][2]) + bb3[3];
            const int so = (tile * 128 + row) * 3;
            g_rgb[so + 0] = 1.0f / (1.0f + expf(-c0));
            g_rgb[so + 1] = 1.0f / (1.0f + expf(-c1));
            g_rgb[so + 2] = 1.0f / (1.0f + expf(-c2));
        }
        __syncwarp();
    }
}

// ---------------------------------------------------------------------------
// Render kernel: one warp per ray, segmented exclusive scan via shfl.
// Output layout: [colors (3R) | distances (R) | opacities (R)].
// ---------------------------------------------------------------------------
__global__ void render_kernel(const float* __restrict__ t_starts,
                              const float* __restrict__ t_ends,
                              float* __restrict__ out)
{
    const int gtid = blockIdx.x * blockDim.x + threadIdx.x;
    const int ray  = gtid >> 5;
    const int lane = threadIdx.x & 31;
    if (ray >= N_RAYS) return;

    const int s = g_off[ray];
    const int e = g_off[ray + 1];

    float carry = 0.0f;
    float op = 0.0f, dist = 0.0f;
    float c0 = 0.0f, c1 = 0.0f, c2 = 0.0f;

    for (int base = s; base < e; base += 32) {
        const int  idx = base + lane;
        const bool v   = (idx < e);
        float sd = v ? g_sigma_dt[idx] : 0.0f;

        float x = sd;
        #pragma unroll
        for (int o = 1; o < 32; o <<= 1) {
            float y = __shfl_up_sync(0xffffffffu, x, o);
            if (lane >= o) x += y;
        }
        const float excl = carry + x - sd;
        carry += __shfl_sync(0xffffffffu, x, 31);

        if (v) {
            const float alpha = -expm1f(-sd);
            const float w     = expf(-excl) * alpha;
            const float m     = 0.5f * (t_starts[idx] + t_ends[idx]);
            op   += w;
            dist += w * m;
            c0 += w * g_rgb[idx * 3 + 0];
            c1 += w * g_rgb[idx * 3 + 1];
            c2 += w * g_rgb[idx * 3 + 2];
        }
    }

    #pragma unroll
    for (int o = 16; o > 0; o >>= 1) {
        op   += __shfl_down_sync(0xffffffffu, op,   o);
        dist += __shfl_down_sync(0xffffffffu, dist, o);
        c0   += __shfl_down_sync(0xffffffffu, c0,   o);
        c1   += __shfl_down_sync(0xffffffffu, c1,   o);
        c2   += __shfl_down_sync(0xffffffffu, c2,   o);
    }

    if (lane == 0) {
        const float rest = 1.0f - op;
        out[ray * 3 + 0] = c0 + 0.5f * rest;
        out[ray * 3 + 1] = c1 + 0.5f * rest;
        out[ray * 3 + 2] = c2 + 0.5f * rest;
        out[3 * N_RAYS + ray] = dist + 5.0f * rest;
        out[4 * N_RAYS + ray] = op;
    }
}

// ---------------------------------------------------------------------------
extern "C" void kernel_launch(void* const* d_in, const int* in_sizes, int n_in,
                              void* d_out, int out_size)
{
    const float* rays_o      = (const float*)d_in[0];
    const float* rays_d      = (const float*)d_in[1];
    const float* t_starts    = (const float*)d_in[2];
    const float* t_ends      = (const float*)d_in[3];
    const int*   ray_indices = (const int*)  d_in[4];
    const float* W_d1 = (const float*)d_in[5];
    const float* b_d1 = (const float*)d_in[6];
    const float* W_d2 = (const float*)d_in[7];
    const float* b_d2 = (const float*)d_in[8];
    const float* W_d3 = (const float*)d_in[9];
    const float* b_d3 = (const float*)d_in[10];
    const float* W_r1 = (const float*)d_in[11];
    const float* b_r1 = (const float*)d_in[12];
    const float* W_r2 = (const float*)d_in[13];
    const float* b_r2 = (const float*)d_in[14];
    const float* W_r3 = (const float*)d_in[15];
    const float* b_r3 = (const float*)d_in[16];
    float* out = (float*)d_out;

    cudaFuncSetAttribute((const void*)mlp_tc_kernel,
                         cudaFuncAttributeMaxDynamicSharedMemorySize, SMEM_TOTAL);

    mlp_tc_kernel<<<GRID_MLP, 128, SMEM_TOTAL>>>(
        rays_o, rays_d, t_starts, t_ends, ray_indices,
        W_d1, b_d1, W_d2, b_d2, W_d3, b_d3,
        W_r1, b_r1, W_r2, b_r2, W_r3, b_r3);

    render_kernel<<<(N_RAYS * 32) / 256, 256>>>(t_starts, t_ends, out);
}

// round 10
// speedup vs baseline: 5.2295x; 1.3738x over previous
#include <cuda_runtime.h>
#include <cuda_fp16.h>
#include <math.h>
#include <stdint.h>

#define N_RAYS 32768
#define N_SAMPLES 1048576
#define N_TILES (N_SAMPLES / 128)
#define GRID_MLP 740
#define ASTRIDE 144              // 64 fp16 = 128B data + 16B pad (16B-aligned rows, 4-bank shift)

// Scratch (device globals; no allocation anywhere)
__device__ float g_sigma_dt[N_SAMPLES];
__device__ float g_rgb[N_SAMPLES * 3];
__device__ int   g_off[N_RAYS + 1];

// ---------------- dynamic SMEM layout (bytes) ----------------
#define A_H    0                 // 128 rows x 144B  activations fp16
#define WT_DH  18432             // 64 rows x 144B  W2d^T fp16  (Wt[n][k])
#define WT_RH  27648             // W2r^T fp16
#define C_W1D  36864             // 192 f32
#define C_W1R  37632
#define C_B1D  38400             // 64 f32 each
#define C_B1R  38656
#define C_B2D  38912
#define C_B2R  39168
#define C_W3D  39424
#define C_W3R  39680             // 192 f32 col-major [ch*64+n]
#define C_B3   40448             // [0]=bd3, [1..3]=br3
#define C_SDT  40464             // 128 f32 dt per tile row
#define SMEM_TOTAL 40992

// ---------------- PTX helpers ----------------
static __device__ __forceinline__ uint32_t smem_u32(const void* p) {
    uint32_t a;
    asm("{ .reg .u64 t; cvta.to.shared.u64 t, %1; cvt.u32.u64 %0, t; }" : "=r"(a) : "l"(p));
    return a;
}
static __device__ __forceinline__ void ldsm_x4(uint32_t* r, uint32_t addr) {
    asm volatile("ldmatrix.sync.aligned.m8n8.x4.shared.b16 {%0,%1,%2,%3}, [%4];"
                 : "=r"(r[0]), "=r"(r[1]), "=r"(r[2]), "=r"(r[3]) : "r"(addr));
}
static __device__ __forceinline__ void ldsm_x2(uint32_t* r, uint32_t addr) {
    asm volatile("ldmatrix.sync.aligned.m8n8.x2.shared.b16 {%0,%1}, [%2];"
                 : "=r"(r[0]), "=r"(r[1]) : "r"(addr));
}
static __device__ __forceinline__ void mma16816(float* c, const uint32_t* a, const uint32_t* b) {
    asm volatile("mma.sync.aligned.m16n8k16.row.col.f32.f16.f16.f32 "
                 "{%0,%1,%2,%3}, {%4,%5,%6,%7}, {%8,%9}, {%0,%1,%2,%3};"
                 : "+f"(c[0]), "+f"(c[1]), "+f"(c[2]), "+f"(c[3])
                 : "r"(a[0]), "r"(a[1]), "r"(a[2]), "r"(a[3]), "r"(b[0]), "r"(b[1]));
}
static __device__ __forceinline__ uint32_t h2_u32(__half2 h) {
    return *reinterpret_cast<uint32_t*>(&h);
}

// ---------------------------------------------------------------------------
// Layer-1 (3 -> 64) scalar + fp16 store of one A row (stride 144B).
// ---------------------------------------------------------------------------
static __device__ __forceinline__ void l1_store(char* smem, int w1off, int b1off,
                                                int t, float p0, float p1, float p2)
{
    const float4* W0 = (const float4*)(smem + w1off);
    const float4* W1 = (const float4*)(smem + w1off + 256);
    const float4* W2 = (const float4*)(smem + w1off + 512);
    const float4* B  = (const float4*)(smem + b1off);
    char* rowH = smem + A_H + t * ASTRIDE;
    #pragma unroll
    for (int g = 0; g < 8; g++) {
        uint32_t hi[4];
        #pragma unroll
        for (int q = 0; q < 2; q++) {
            int j = g * 2 + q;
            float4 w0 = W0[j], w1 = W1[j], w2 = W2[j], b = B[j];
            float h0 = fmaxf(fmaf(p2, w2.x, fmaf(p1, w1.x, fmaf(p0, w0.x, b.x))), 0.0f);
            float h1 = fmaxf(fmaf(p2, w2.y, fmaf(p1, w1.y, fmaf(p0, w0.y, b.y))), 0.0f);
            float h2 = fmaxf(fmaf(p2, w2.z, fmaf(p1, w1.z, fmaf(p0, w0.z, b.z))), 0.0f);
            float h3 = fmaxf(fmaf(p2, w2.w, fmaf(p1, w1.w, fmaf(p0, w0.w, b.w))), 0.0f);
            hi[2*q+0] = h2_u32(__floats2half2_rn(h0, h1));
            hi[2*q+1] = h2_u32(__floats2half2_rn(h2, h3));
        }
        *(uint4*)(rowH + g * 16) = make_uint4(hi[0], hi[1], hi[2], hi[3]);
    }
}

// ---------------------------------------------------------------------------
// Layer-2 via mma.sync: warp computes its 32 rows x 64 cols, K=64, fp16.
// ---------------------------------------------------------------------------
static __device__ __forceinline__ void run_net(
    uint32_t sb, int bHoff, int m0,
    uint32_t aoff, uint32_t boff, float acc[2][8][4])
{
    #pragma unroll
    for (int mb = 0; mb < 2; mb++)
        #pragma unroll
        for (int n = 0; n < 8; n++)
            #pragma unroll
            for (int e = 0; e < 4; e++) acc[mb][n][e] = 0.0f;

    #pragma unroll
    for (int k = 0; k < 4; k++) {
        uint32_t ah0[4], ah1[4];
        const uint32_t aH = sb + A_H + (uint32_t)(m0 * ASTRIDE) + k * 32 + aoff;
        ldsm_x4(ah0, aH);
        ldsm_x4(ah1, aH + 16 * ASTRIDE);
        #pragma unroll
        for (int n = 0; n < 8; n++) {
            uint32_t bh[2];
            ldsm_x2(bh, sb + bHoff + n * 8 * ASTRIDE + k * 32 + boff);
            mma16816(acc[0][n], ah0, bh);
            mma16816(acc[1][n], ah1, bh);
        }
    }
}

// ---------------------------------------------------------------------------
// Fused MLP kernel: persistent CTAs, 128-sample tiles, warp-synchronous.
// Also scatters per-ray segment offsets (ray_indices sorted) on the fly.
// ---------------------------------------------------------------------------
__global__ void __launch_bounds__(128) mlp_tc_kernel(
    const float* __restrict__ rays_o, const float* __restrict__ rays_d,
    const float* __restrict__ t_starts, const float* __restrict__ t_ends,
    const int*   __restrict__ ray_indices,
    const float* __restrict__ Wd1, const float* __restrict__ bd1,
    const float* __restrict__ Wd2, const float* __restrict__ bd2,
    const float* __restrict__ Wd3, const float* __restrict__ bd3,
    const float* __restrict__ Wr1, const float* __restrict__ br1,
    const float* __restrict__ Wr2, const float* __restrict__ br2,
    const float* __restrict__ Wr3, const float* __restrict__ br3)
{
    extern __shared__ char smem[];
    const uint32_t sb = smem_u32(smem);
    const int t    = threadIdx.x;
    const int lane = t & 31;
    const int wid  = t >> 5;
    const int m0   = wid * 32;

    // -------- one-time weight prep --------
    {
        float* w1d = (float*)(smem + C_W1D);
        float* w1r = (float*)(smem + C_W1R);
        float* w3r = (float*)(smem + C_W3R);
        for (int i = t; i < 192; i += 128) {
            w1d[i] = Wd1[i]; w1r[i] = Wr1[i];
            w3r[(i % 3) * 64 + (i / 3)] = Wr3[i];     // col-major [ch*64+n]
        }
        if (t < 64) {
            ((float*)(smem + C_B1D))[t] = bd1[t];
            ((float*)(smem + C_B1R))[t] = br1[t];
            ((float*)(smem + C_B2D))[t] = bd2[t];
            ((float*)(smem + C_B2R))[t] = br2[t];
            ((float*)(smem + C_W3D))[t] = Wd3[t];
        }
        if (t == 0) ((float*)(smem + C_B3))[0] = bd3[0];
        if (t < 3)  ((float*)(smem + C_B3))[1 + t] = br3[t];
        // W2 -> Wt[n][k] = W2[k][n], single fp16, stride 144B
        for (int idx = t; idx < 4096; idx += 128) {
            int k = idx >> 6, n = idx & 63;
            int off = n * ASTRIDE + k * 2;
            *(__half*)(smem + WT_DH + off) = __float2half_rn(Wd2[idx]);
            *(__half*)(smem + WT_RH + off) = __float2half_rn(Wr2[idx]);
        }
    }
    __syncthreads();

    // per-lane ldmatrix offsets
    const uint32_t aoff = (uint32_t)(((lane & 7) + ((lane >> 3) & 1) * 8) * ASTRIDE
                                     + ((lane >> 4) & 1) * 16);
    const int l16 = lane & 15;
    const uint32_t boff = (uint32_t)((l16 & 7) * ASTRIDE + ((l16 >> 3) & 1) * 16);

    const float* b2d = (const float*)(smem + C_B2D);
    const float* b2r = (const float*)(smem + C_B2R);
    const float* w3d = (const float*)(smem + C_W3D);
    const float* w3r = (const float*)(smem + C_W3R);
    const float* bb3 = (const float*)(smem + C_B3);
    float* sdt = (float*)(smem + C_SDT);

    const int j   = lane & 3;
    const int row = m0 + (lane >> 2) + 8 * j;   // output row this thread owns

    for (int tile = blockIdx.x; tile < N_TILES; tile += gridDim.x) {
        const int s  = tile * 128 + t;
        const int ri = ray_indices[s];

        // fused per-ray offset scatter (ray_indices sorted)
        {
            const int prev = (s == 0) ? -1 : ray_indices[s - 1];
            for (int r = prev + 1; r <= ri; r++) g_off[r] = s;
            if (s == N_SAMPLES - 1)
                for (int r = ri + 1; r <= N_RAYS; r++) g_off[r] = N_SAMPLES;
        }

        const float ts_ = t_starts[s], te_ = t_ends[s];
        const float mid = 0.5f * (ts_ + te_);
        const float p0 = fmaf(rays_d[ri * 3 + 0], mid, rays_o[ri * 3 + 0]);
        const float p1 = fmaf(rays_d[ri * 3 + 1], mid, rays_o[ri * 3 + 1]);
        const float p2 = fmaf(rays_d[ri * 3 + 2], mid, rays_o[ri * 3 + 2]);
        sdt[t] = te_ - ts_;

        // ================= density net =================
        l1_store(smem, C_W1D, C_B1D, t, p0, p1, p2);
        __syncwarp();
        {
            float acc[2][8][4];
            run_net(sb, WT_DH, m0, aoff, boff, acc);
            float s0 = 0.f, s1 = 0.f, s2 = 0.f, s3 = 0.f;
            #pragma unroll
            for (int n = 0; n < 8; n++) {
                const int cA = n * 8 + 2 * j;
                const float ba = b2d[cA], bb = b2d[cA + 1];
                const float wa = w3d[cA], wb = w3d[cA + 1];
                s0 = fmaf(fmaxf(acc[0][n][0] + ba, 0.f), wa, fmaf(fmaxf(acc[0][n][1] + bb, 0.f), wb, s0));
                s1 = fmaf(fmaxf(acc[0][n][2] + ba, 0.f), wa, fmaf(fmaxf(acc[0][n][3] + bb, 0.f), wb, s1));
                s2 = fmaf(fmaxf(acc[1][n][0] + ba, 0.f), wa, fmaf(fmaxf(acc[1][n][1] + bb, 0.f), wb, s2));
                s3 = fmaf(fmaxf(acc[1][n][2] + ba, 0.f), wa, fmaf(fmaxf(acc[1][n][3] + bb, 0.f), wb, s3));
            }
            s0 += __shfl_xor_sync(0xffffffffu, s0, 1); s0 += __shfl_xor_sync(0xffffffffu, s0, 2);
            s1 += __shfl_xor_sync(0xffffffffu, s1, 1); s1 += __shfl_xor_sync(0xffffffffu, s1, 2);
            s2 += __shfl_xor_sync(0xffffffffu, s2, 1); s2 += __shfl_xor_sync(0xffffffffu, s2, 2);
            s3 += __shfl_xor_sync(0xffffffffu, s3, 1); s3 += __shfl_xor_sync(0xffffffffu, s3, 2);
            const float sl = ((j == 0) ? s0 : (j == 1) ? s1 : (j == 2) ? s2 : s3) + bb3[0];
            const float sigma = fmaxf(sl, 0.0f) + log1pf(expf(-fabsf(sl)));
            g_sigma_dt[tile * 128 + row] = sigma * sdt[row];
        }
        __syncwarp();

        // ================= rgb net =================
        l1_store(smem, C_W1R, C_B1R, t, p0, p1, p2);
        __syncwarp();
        {
            float acc[2][8][4];
            run_net(sb, WT_RH, m0, aoff, boff, acc);
            float rr[4][3];
            #pragma unroll
            for (int q = 0; q < 4; q++) { rr[q][0] = 0.f; rr[q][1] = 0.f; rr[q][2] = 0.f; }
            #pragma unroll
            for (int n = 0; n < 8; n++) {
                const int cA = n * 8 + 2 * j;
                const float ba = b2r[cA], bb = b2r[cA + 1];
                const float wa0 = w3r[cA],        wb0 = w3r[cA + 1];
                const float wa1 = w3r[64 + cA],   wb1 = w3r[64 + cA + 1];
                const float wa2 = w3r[128 + cA],  wb2 = w3r[128 + cA + 1];
                #pragma unroll
                for (int mb = 0; mb < 2; mb++) {
                    const float hA0 = fmaxf(acc[mb][n][0] + ba, 0.f);
                    const float hB0 = fmaxf(acc[mb][n][1] + bb, 0.f);
                    const float hA1 = fmaxf(acc[mb][n][2] + ba, 0.f);
                    const float hB1 = fmaxf(acc[mb][n][3] + bb, 0.f);
                    rr[mb*2+0][0] = fmaf(hA0, wa0, fmaf(hB0, wb0, rr[mb*2+0][0]));
                    rr[mb*2+0][1] = fmaf(hA0, wa1, fmaf(hB0, wb1, rr[mb*2+0][1]));
                    rr[mb*2+0][2] = fmaf(hA0, wa2, fmaf(hB0, wb2, rr[mb*2+0][2]));
                    rr[mb*2+1][0] = fmaf(hA1, wa0, fmaf(hB1, wb0, rr[mb*2+1][0]));
                    rr[mb*2+1][1] = fmaf(hA1, wa1, fmaf(hB1, wb1, rr[mb*2+1][1]));
                    rr[mb*2+1][2] = fmaf(hA1, wa2, fmaf(hB1, wb2, rr[mb*2+1][2]));
                }
            }
            #pragma unroll
            for (int q = 0; q < 4; q++)
                #pragma unroll
                for (int ch = 0; ch < 3; ch++) {
                    rr[q][ch] += __shfl_xor_sync(0xffffffffu, rr[q][ch], 1);
                    rr[q][ch] += __shfl_xor_sync(0xffffffffu, rr[q][ch], 2);
                }
            const float c0 = ((j==0)?rr[0][0]:(j==1)?rr[1][0]:(j==2)?rr[2][0]:rr[3][0]) + bb3[1];
            const float c1 = ((j==0)?rr[0][1]:(j==1)?rr[1][1]:(j==2)?rr[2][1]:rr[3][1]) + bb3[2];
            const float c2 = ((j==0)?rr[0][2]:(j==1)?rr[1][2]:(j==2)?rr[2][2]:rr[3][2]) + bb3[3];
            const int so = (tile * 128 + row) * 3;
            g_rgb[so + 0] = 1.0f / (1.0f + expf(-c0));
            g_rgb[so + 1] = 1.0f / (1.0f + expf(-c1));
            g_rgb[so + 2] = 1.0f / (1.0f + expf(-c2));
        }
        __syncwarp();
    }
}

// ---------------------------------------------------------------------------
// Render kernel: one warp per ray, segmented exclusive scan via shfl.
// Output layout: [colors (3R) | distances (R) | opacities (R)].
// ---------------------------------------------------------------------------
__global__ void render_kernel(const float* __restrict__ t_starts,
                              const float* __restrict__ t_ends,
                              float* __restrict__ out)
{
    const int gtid = blockIdx.x * blockDim.x + threadIdx.x;
    const int ray  = gtid >> 5;
    const int lane = threadIdx.x & 31;
    if (ray >= N_RAYS) return;

    const int s = g_off[ray];
    const int e = g_off[ray + 1];

    float carry = 0.0f;
    float op = 0.0f, dist = 0.0f;
    float c0 = 0.0f, c1 = 0.0f, c2 = 0.0f;

    for (int base = s; base < e; base += 32) {
        const int  idx = base + lane;
        const bool v   = (idx < e);
        float sd = v ? g_sigma_dt[idx] : 0.0f;

        float x = sd;
        #pragma unroll
        for (int o = 1; o < 32; o <<= 1) {
            float y = __shfl_up_sync(0xffffffffu, x, o);
            if (lane >= o) x += y;
        }
        const float excl = carry + x - sd;
        carry += __shfl_sync(0xffffffffu, x, 31);

        if (v) {
            const float alpha = -expm1f(-sd);
            const float w     = expf(-excl) * alpha;
            const float m     = 0.5f * (t_starts[idx] + t_ends[idx]);
            op   += w;
            dist += w * m;
            c0 += w * g_rgb[idx * 3 + 0];
            c1 += w * g_rgb[idx * 3 + 1];
            c2 += w * g_rgb[idx * 3 + 2];
        }
    }

    #pragma unroll
    for (int o = 16; o > 0; o >>= 1) {
        op   += __shfl_down_sync(0xffffffffu, op,   o);
        dist += __shfl_down_sync(0xffffffffu, dist, o);
        c0   += __shfl_down_sync(0xffffffffu, c0,   o);
        c1   += __shfl_down_sync(0xffffffffu, c1,   o);
        c2   += __shfl_down_sync(0xffffffffu, c2,   o);
    }

    if (lane == 0) {
        const float rest = 1.0f - op;
        out[ray * 3 + 0] = c0 + 0.5f * rest;
        out[ray * 3 + 1] = c1 + 0.5f * rest;
        out[ray * 3 + 2] = c2 + 0.5f * rest;
        out[3 * N_RAYS + ray] = dist + 5.0f * rest;
        out[4 * N_RAYS + ray] = op;
    }
}

// ---------------------------------------------------------------------------
extern "C" void kernel_launch(void* const* d_in, const int* in_sizes, int n_in,
                              void* d_out, int out_size)
{
    const float* rays_o      = (const float*)d_in[0];
    const float* rays_d      = (const float*)d_in[1];
    const float* t_starts    = (const float*)d_in[2];
    const float* t_ends      = (const float*)d_in[3];
    const int*   ray_indices = (const int*)  d_in[4];
    const float* W_d1 = (const float*)d_in[5];
    const float* b_d1 = (const float*)d_in[6];
    const float* W_d2 = (const float*)d_in[7];
    const float* b_d2 = (const float*)d_in[8];
    const float* W_d3 = (const float*)d_in[9];
    const float* b_d3 = (const float*)d_in[10];
    const float* W_r1 = (const float*)d_in[11];
    const float* b_r1 = (const float*)d_in[12];
    const float* W_r2 = (const float*)d_in[13];
    const float* b_r2 = (const float*)d_in[14];
    const float* W_r3 = (const float*)d_in[15];
    const float* b_r3 = (const float*)d_in[16];
    float* out = (float*)d_out;

    cudaFuncSetAttribute((const void*)mlp_tc_kernel,
                         cudaFuncAttributeMaxDynamicSharedMemorySize, SMEM_TOTAL);

    mlp_tc_kernel<<<GRID_MLP, 128, SMEM_TOTAL>>>(
        rays_o, rays_d, t_starts, t_ends, ray_indices,
        W_d1, b_d1, W_d2, b_d2, W_d3, b_d3,
        W_r1, b_r1, W_r2, b_r2, W_r3, b_r3);

    render_kernel<<<(N_RAYS * 32) / 256, 256>>>(t_starts, t_ends, out);
}

// round 13
// speedup vs baseline: 5.3061x; 1.0146x over previous
#include <cuda_runtime.h>
#include <cuda_fp16.h>
#include <math.h>
#include <stdint.h>

#define N_RAYS 32768
#define N_SAMPLES 1048576
#define N_TILES (N_SAMPLES / 128)
#define GRID_MLP 592             // 148 SMs x 4 CTAs: exactly one wave
#define ASTRIDE 144              // 64 fp16 = 128B data + 16B pad

// Scratch (device globals; no allocation anywhere)
__device__ float g_sigma_dt[N_SAMPLES];
__device__ float g_rgb[N_SAMPLES * 3];
__device__ int   g_off[N_RAYS + 1];

// ---------------- dynamic SMEM layout (bytes) ----------------
#define A_H    0                 // 128 rows x 144B  activations fp16
#define WT_DH  18432             // 64 rows x 144B  W2d^T fp16  (Wt[n][k])
#define WT_RH  27648             // W2r^T fp16
#define C_W1D  36864             // 192 f32
#define C_W1R  37632
#define C_B1D  38400             // 64 f32 each
#define C_B1R  38656
#define C_B2D  38912
#define C_B2R  39168
#define C_W3D  39424
#define C_W3R  39680             // 192 f32 col-major [ch*64+n]
#define C_B3   40448             // [0]=bd3, [1..3]=br3
#define C_SDT  40464             // 128 f32 dt per tile row
#define SMEM_TOTAL 40992

// ---------------- PTX helpers ----------------
static __device__ __forceinline__ uint32_t smem_u32(const void* p) {
    uint32_t a;
    asm("{ .reg .u64 t; cvta.to.shared.u64 t, %1; cvt.u32.u64 %0, t; }" : "=r"(a) : "l"(p));
    return a;
}
static __device__ __forceinline__ void ldsm_x4(uint32_t* r, uint32_t addr) {
    asm volatile("ldmatrix.sync.aligned.m8n8.x4.shared.b16 {%0,%1,%2,%3}, [%4];"
                 : "=r"(r[0]), "=r"(r[1]), "=r"(r[2]), "=r"(r[3]) : "r"(addr));
}
static __device__ __forceinline__ void mma16816(float* c, const uint32_t* a, const uint32_t* b) {
    asm volatile("mma.sync.aligned.m16n8k16.row.col.f32.f16.f16.f32 "
                 "{%0,%1,%2,%3}, {%4,%5,%6,%7}, {%8,%9}, {%0,%1,%2,%3};"
                 : "+f"(c[0]), "+f"(c[1]), "+f"(c[2]), "+f"(c[3])
                 : "r"(a[0]), "r"(a[1]), "r"(a[2]), "r"(a[3]), "r"(b[0]), "r"(b[1]));
}
static __device__ __forceinline__ uint32_t h2_u32(__half2 h) {
    return *reinterpret_cast<uint32_t*>(&h);
}

// ---------------------------------------------------------------------------
// Layer-1 (3 -> 64) scalar + fp16 store of one A row (stride 144B).
// ---------------------------------------------------------------------------
static __device__ __forceinline__ void l1_store(char* smem, int w1off, int b1off,
                                                int t, float p0, float p1, float p2)
{
    const float4* W0 = (const float4*)(smem + w1off);
    const float4* W1 = (const float4*)(smem + w1off + 256);
    const float4* W2 = (const float4*)(smem + w1off + 512);
    const float4* B  = (const float4*)(smem + b1off);
    char* rowH = smem + A_H + t * ASTRIDE;
    #pragma unroll
    for (int g = 0; g < 8; g++) {
        uint32_t hi[4];
        #pragma unroll
        for (int q = 0; q < 2; q++) {
            int j = g * 2 + q;
            float4 w0 = W0[j], w1 = W1[j], w2 = W2[j], b = B[j];
            float h0 = fmaxf(fmaf(p2, w2.x, fmaf(p1, w1.x, fmaf(p0, w0.x, b.x))), 0.0f);
            float h1 = fmaxf(fmaf(p2, w2.y, fmaf(p1, w1.y, fmaf(p0, w0.y, b.y))), 0.0f);
            float h2 = fmaxf(fmaf(p2, w2.z, fmaf(p1, w1.z, fmaf(p0, w0.z, b.z))), 0.0f);
            float h3 = fmaxf(fmaf(p2, w2.w, fmaf(p1, w1.w, fmaf(p0, w0.w, b.w))), 0.0f);
            hi[2*q+0] = h2_u32(__floats2half2_rn(h0, h1));
            hi[2*q+1] = h2_u32(__floats2half2_rn(h2, h3));
        }
        *(uint4*)(rowH + g * 16) = make_uint4(hi[0], hi[1], hi[2], hi[3]);
    }
}

// ---------------------------------------------------------------------------
// Layer-2 via mma.sync: warp computes its 32 rows x 64 cols, K=64, fp16.
// B fragments loaded two n-tiles at a time via ldmatrix.x4.
// ---------------------------------------------------------------------------
static __device__ __forceinline__ void run_net(
    uint32_t sb, int bHoff, int m0,
    uint32_t aoff, uint32_t boff4, float acc[2][8][4])
{
    #pragma unroll
    for (int mb = 0; mb < 2; mb++)
        #pragma unroll
        for (int n = 0; n < 8; n++)
            #pragma unroll
            for (int e = 0; e < 4; e++) acc[mb][n][e] = 0.0f;

    #pragma unroll
    for (int k = 0; k < 4; k++) {
        uint32_t ah0[4], ah1[4];
        const uint32_t aH = sb + A_H + (uint32_t)(m0 * ASTRIDE) + k * 32 + aoff;
        ldsm_x4(ah0, aH);
        ldsm_x4(ah1, aH + 16 * ASTRIDE);
        #pragma unroll
        for (int np = 0; np < 4; np++) {            // pairs of n-tiles
            uint32_t b4[4];
            ldsm_x4(b4, sb + bHoff + np * 16 * ASTRIDE + k * 32 + boff4);
            mma16816(acc[0][2*np+0], ah0, b4 + 0);
            mma16816(acc[1][2*np+0], ah1, b4 + 0);
            mma16816(acc[0][2*np+1], ah0, b4 + 2);
            mma16816(acc[1][2*np+1], ah1, b4 + 2);
        }
    }
}

// ---------------------------------------------------------------------------
// MLP kernel: persistent single-wave grid, 128-sample tiles, warp-synchronous,
// next-tile input prefetch, fused per-ray offset scatter.
// ---------------------------------------------------------------------------
__global__ void __launch_bounds__(128, 4) mlp_tc_kernel(
    const float* __restrict__ rays_o, const float* __restrict__ rays_d,
    const float* __restrict__ t_starts, const float* __restrict__ t_ends,
    const int*   __restrict__ ray_indices,
    const float* __restrict__ Wd1, const float* __restrict__ bd1,
    const float* __restrict__ Wd2, const float* __restrict__ bd2,
    const float* __restrict__ Wd3, const float* __restrict__ bd3,
    const float* __restrict__ Wr1, const float* __restrict__ br1,
    const float* __restrict__ Wr2, const float* __restrict__ br2,
    const float* __restrict__ Wr3, const float* __restrict__ br3)
{
    extern __shared__ char smem[];
    const uint32_t sb = smem_u32(smem);
    const int t    = threadIdx.x;
    const int lane = t & 31;
    const int wid  = t >> 5;
    const int m0   = wid * 32;

    // -------- one-time weight prep --------
    {
        float* w1d = (float*)(smem + C_W1D);
        float* w1r = (float*)(smem + C_W1R);
        float* w3r = (float*)(smem + C_W3R);
        for (int i = t; i < 192; i += 128) {
            w1d[i] = Wd1[i]; w1r[i] = Wr1[i];
            w3r[(i % 3) * 64 + (i / 3)] = Wr3[i];     // col-major [ch*64+n]
        }
        if (t < 64) {
            ((float*)(smem + C_B1D))[t] = bd1[t];
            ((float*)(smem + C_B1R))[t] = br1[t];
            ((float*)(smem + C_B2D))[t] = bd2[t];
            ((float*)(smem + C_B2R))[t] = br2[t];
            ((float*)(smem + C_W3D))[t] = Wd3[t];
        }
        if (t == 0) ((float*)(smem + C_B3))[0] = bd3[0];
        if (t < 3)  ((float*)(smem + C_B3))[1 + t] = br3[t];
        // W2 -> Wt[n][k] = W2[k][n], single fp16, stride 144B
        for (int idx = t; idx < 4096; idx += 128) {
            int k = idx >> 6, n = idx & 63;
            int off = n * ASTRIDE + k * 2;
            *(__half*)(smem + WT_DH + off) = __float2half_rn(Wd2[idx]);
            *(__half*)(smem + WT_RH + off) = __float2half_rn(Wr2[idx]);
        }
    }
    __syncthreads();

    // per-lane ldmatrix offsets
    const uint32_t aoff = (uint32_t)(((lane & 7) + ((lane >> 3) & 1) * 8) * ASTRIDE
                                     + ((lane >> 4) & 1) * 16);
    // x4 B: lanes 0-7 row lo/k-lo, 8-15 row lo/k-hi, 16-23 row+8/k-lo, 24-31 row+8/k-hi
    const uint32_t boff4 = (uint32_t)(((lane >> 4) & 1) * 8 * ASTRIDE
                                      + (lane & 7) * ASTRIDE + ((lane >> 3) & 1) * 16);

    const float* b2d = (const float*)(smem + C_B2D);
    const float* b2r = (const float*)(smem + C_B2R);
    const float* w3d = (const float*)(smem + C_W3D);
    const float* w3r = (const float*)(smem + C_W3R);
    const float* bb3 = (const float*)(smem + C_B3);
    float* sdt = (float*)(smem + C_SDT);

    const int j   = lane & 3;
    const int row = m0 + (lane >> 2) + 8 * j;   // output row this thread owns

    // -------- persistent tile loop with input prefetch --------
    int tile = blockIdx.x;
    int ri, prev;
    float ts_, te_;
    {
        const int s0 = tile * 128 + t;
        ri   = ray_indices[s0];
        prev = (s0 == 0) ? -1 : ray_indices[s0 - 1];
        ts_  = t_starts[s0];
        te_  = t_ends[s0];
    }

    for (;;) {
        const int tile_n = tile + (int)gridDim.x;
        const bool has_next = tile_n < N_TILES;
        int ri_n = 0, prev_n = 0;
        float ts_n = 0.f, te_n = 0.f;
        if (has_next) {                       // prefetch next tile's inputs
            const int sn = tile_n * 128 + t;
            ri_n   = ray_indices[sn];
            prev_n = ray_indices[sn - 1];     // sn >= 128, safe
            ts_n   = t_starts[sn];
            te_n   = t_ends[sn];
        }

        const int s = tile * 128 + t;

        // fused per-ray offset scatter (ray_indices sorted)
        for (int r = prev + 1; r <= ri; r++) g_off[r] = s;
        if (s == N_SAMPLES - 1)
            for (int r = ri + 1; r <= N_RAYS; r++) g_off[r] = N_SAMPLES;

        const float mid = 0.5f * (ts_ + te_);
        const float p0 = fmaf(rays_d[ri * 3 + 0], mid, rays_o[ri * 3 + 0]);
        const float p1 = fmaf(rays_d[ri * 3 + 1], mid, rays_o[ri * 3 + 1]);
        const float p2 = fmaf(rays_d[ri * 3 + 2], mid, rays_o[ri * 3 + 2]);
        sdt[t] = te_ - ts_;

        // ================= density net =================
        l1_store(smem, C_W1D, C_B1D, t, p0, p1, p2);
        __syncwarp();
        {
            float acc[2][8][4];
            run_net(sb, WT_DH, m0, aoff, boff4, acc);
            float s0 = 0.f, s1 = 0.f, s2 = 0.f, s3 = 0.f;
            #pragma unroll
            for (int n = 0; n < 8; n++) {
                const int cA = n * 8 + 2 * j;
                const float ba = b2d[cA], bb = b2d[cA + 1];
                const float wa = w3d[cA], wb = w3d[cA + 1];
                s0 = fmaf(fmaxf(acc[0][n][0] + ba, 0.f), wa, fmaf(fmaxf(acc[0][n][1] + bb, 0.f), wb, s0));
                s1 = fmaf(fmaxf(acc[0][n][2] + ba, 0.f), wa, fmaf(fmaxf(acc[0][n][3] + bb, 0.f), wb, s1));
                s2 = fmaf(fmaxf(acc[1][n][0] + ba, 0.f), wa, fmaf(fmaxf(acc[1][n][1] + bb, 0.f), wb, s2));
                s3 = fmaf(fmaxf(acc[1][n][2] + ba, 0.f), wa, fmaf(fmaxf(acc[1][n][3] + bb, 0.f), wb, s3));
            }
            s0 += __shfl_xor_sync(0xffffffffu, s0, 1); s0 += __shfl_xor_sync(0xffffffffu, s0, 2);
            s1 += __shfl_xor_sync(0xffffffffu, s1, 1); s1 += __shfl_xor_sync(0xffffffffu, s1, 2);
            s2 += __shfl_xor_sync(0xffffffffu, s2, 1); s2 += __shfl_xor_sync(0xffffffffu, s2, 2);
            s3 += __shfl_xor_sync(0xffffffffu, s3, 1); s3 += __shfl_xor_sync(0xffffffffu, s3, 2);
            const float sl = ((j == 0) ? s0 : (j == 1) ? s1 : (j == 2) ? s2 : s3) + bb3[0];
            const float sigma = fmaxf(sl, 0.0f) + log1pf(expf(-fabsf(sl)));
            g_sigma_dt[tile * 128 + row] = sigma * sdt[row];
        }
        __syncwarp();

        // ================= rgb net =================
        l1_store(smem, C_W1R, C_B1R, t, p0, p1, p2);
        __syncwarp();
        {
            float acc[2][8][4];
            run_net(sb, WT_RH, m0, aoff, boff4, acc);
            float rr[4][3];
            #pragma unroll
            for (int q = 0; q < 4; q++) { rr[q][0] = 0.f; rr[q][1] = 0.f; rr[q][2] = 0.f; }
            #pragma unroll
            for (int n = 0; n < 8; n++) {
                const int cA = n * 8 + 2 * j;
                const float ba = b2r[cA], bb = b2r[cA + 1];
                const float wa0 = w3r[cA],        wb0 = w3r[cA + 1];
                const float wa1 = w3r[64 + cA],   wb1 = w3r[64 + cA + 1];
                const float wa2 = w3r[128 + cA],  wb2 = w3r[128 + cA + 1];
                #pragma unroll
                for (int mb = 0; mb < 2; mb++) {
                    const float hA0 = fmaxf(acc[mb][n][0] + ba, 0.f);
                    const float hB0 = fmaxf(acc[mb][n][1] + bb, 0.f);
                    const float hA1 = fmaxf(acc[mb][n][2] + ba, 0.f);
                    const float hB1 = fmaxf(acc[mb][n][3] + bb, 0.f);
                    rr[mb*2+0][0] = fmaf(hA0, wa0, fmaf(hB0, wb0, rr[mb*2+0][0]));
                    rr[mb*2+0][1] = fmaf(hA0, wa1, fmaf(hB0, wb1, rr[mb*2+0][1]));
                    rr[mb*2+0][2] = fmaf(hA0, wa2, fmaf(hB0, wb2, rr[mb*2+0][2]));
                    rr[mb*2+1][0] = fmaf(hA1, wa0, fmaf(hB1, wb0, rr[mb*2+1][0]));
                    rr[mb*2+1][1] = fmaf(hA1, wa1, fmaf(hB1, wb1, rr[mb*2+1][1]));
                    rr[mb*2+1][2] = fmaf(hA1, wa2, fmaf(hB1, wb2, rr[mb*2+1][2]));
                }
            }
            #pragma unroll
            for (int q = 0; q < 4; q++)
                #pragma unroll
                for (int ch = 0; ch < 3; ch++) {
                    rr[q][ch] += __shfl_xor_sync(0xffffffffu, rr[q][ch], 1);
                    rr[q][ch] += __shfl_xor_sync(0xffffffffu, rr[q][ch], 2);
                }
            const float c0 = ((j==0)?rr[0][0]:(j==1)?rr[1][0]:(j==2)?rr[2][0]:rr[3][0]) + bb3[1];
            const float c1 = ((j==0)?rr[0][1]:(j==1)?rr[1][1]:(j==2)?rr[2][1]:rr[3][1]) + bb3[2];
            const float c2 = ((j==0)?rr[0][2]:(j==1)?rr[1][2]:(j==2)?rr[2][2]:rr[3][2]) + bb3[3];
            const int so = (tile * 128 + row) * 3;
            g_rgb[so + 0] = 1.0f / (1.0f + expf(-c0));
            g_rgb[so + 1] = 1.0f / (1.0f + expf(-c1));
            g_rgb[so + 2] = 1.0f / (1.0f + expf(-c2));
        }
        __syncwarp();

        if (!has_next) break;
        tile = tile_n; ri = ri_n; prev = prev_n; ts_ = ts_n; te_ = te_n;
    }
}

// ---------------------------------------------------------------------------
// Render kernel: one warp per ray, segmented exclusive scan via shfl.
// Output layout: [colors (3R) | distances (R) | opacities (R)].
// ---------------------------------------------------------------------------
__global__ void render_kernel(const float* __restrict__ t_starts,
                              const float* __restrict__ t_ends,
                              float* __restrict__ out)
{
    const int gtid = blockIdx.x * blockDim.x + threadIdx.x;
    const int ray  = gtid >> 5;
    const int lane = threadIdx.x & 31;
    if (ray >= N_RAYS) return;

    const int s = g_off[ray];
    const int e = g_off[ray + 1];

    float carry = 0.0f;
    float op = 0.0f, dist = 0.0f;
    float c0 = 0.0f, c1 = 0.0f, c2 = 0.0f;

    for (int base = s; base < e; base += 32) {
        const int  idx = base + lane;
        const bool v   = (idx < e);
        float sd = v ? g_sigma_dt[idx] : 0.0f;

        float x = sd;
        #pragma unroll
        for (int o = 1; o < 32; o <<= 1) {
            float y = __shfl_up_sync(0xffffffffu, x, o);
            if (lane >= o) x += y;
        }
        const float excl = carry + x - sd;
        carry += __shfl_sync(0xffffffffu, x, 31);

        if (v) {
            const float alpha = -expm1f(-sd);
            const float w     = expf(-excl) * alpha;
            const float m     = 0.5f * (t_starts[idx] + t_ends[idx]);
            op   += w;
            dist += w * m;
            c0 += w * g_rgb[idx * 3 + 0];
            c1 += w * g_rgb[idx * 3 + 1];
            c2 += w * g_rgb[idx * 3 + 2];
        }
    }

    #pragma unroll
    for (int o = 16; o > 0; o >>= 1) {
        op   += __shfl_down_sync(0xffffffffu, op,   o);
        dist += __shfl_down_sync(0xffffffffu, dist, o);
        c0   += __shfl_down_sync(0xffffffffu, c0,   o);
        c1   += __shfl_down_sync(0xffffffffu, c1,   o);
        c2   += __shfl_down_sync(0xffffffffu, c2,   o);
    }

    if (lane == 0) {
        const float rest = 1.0f - op;
        out[ray * 3 + 0] = c0 + 0.5f * rest;
        out[ray * 3 + 1] = c1 + 0.5f * rest;
        out[ray * 3 + 2] = c2 + 0.5f * rest;
        out[3 * N_RAYS + ray] = dist + 5.0f * rest;
        out[4 * N_RAYS + ray] = op;
    }
}

// ---------------------------------------------------------------------------
extern "C" void kernel_launch(void* const* d_in, const int* in_sizes, int n_in,
                              void* d_out, int out_size)
{
    const float* rays_o      = (const float*)d_in[0];
    const float* rays_d      = (const float*)d_in[1];
    const float* t_starts    = (const float*)d_in[2];
    const float* t_ends      = (const float*)d_in[3];
    const int*   ray_indices = (const int*)  d_in[4];
    const float* W_d1 = (const float*)d_in[5];
    const float* b_d1 = (const float*)d_in[6];
    const float* W_d2 = (const float*)d_in[7];
    const float* b_d2 = (const float*)d_in[8];
    const float* W_d3 = (const float*)d_in[9];
    const float* b_d3 = (const float*)d_in[10];
    const float* W_r1 = (const float*)d_in[11];
    const float* b_r1 = (const float*)d_in[12];
    const float* W_r2 = (const float*)d_in[13];
    const float* b_r2 = (const float*)d_in[14];
    const float* W_r3 = (const float*)d_in[15];
    const float* b_r3 = (const float*)d_in[16];
    float* out = (float*)d_out;

    cudaFuncSetAttribute((const void*)mlp_tc_kernel,
                         cudaFuncAttributeMaxDynamicSharedMemorySize, SMEM_TOTAL);

    mlp_tc_kernel<<<GRID_MLP, 128, SMEM_TOTAL>>>(
        rays_o, rays_d, t_starts, t_ends, ray_indices,
        W_d1, b_d1, W_d2, b_d2, W_d3, b_d3,
        W_r1, b_r1, W_r2, b_r2, W_r3, b_r3);

    render_kernel<<<(N_RAYS * 32) / 256, 256>>>(t_starts, t_ends, out);
}

// round 15
// speedup vs baseline: 6.2379x; 1.1756x over previous
#include <cuda_runtime.h>
#include <cuda_fp16.h>
#include <math.h>
#include <stdint.h>

#define N_RAYS 32768
#define N_SAMPLES 1048576
#define N_TILES (N_SAMPLES / 128)
#define GRID_MLP 592             // 148 SMs x 4 CTAs: single wave
#define ASTRIDE 144              // 64 fp16 = 128B data + 16B pad

// Scratch (device globals; no allocation anywhere)
__device__ float g_sigma_dt[N_SAMPLES];
__device__ float g_rgb[N_SAMPLES * 3];
__device__ int   g_off[N_RAYS + 1];

// ---------------- dynamic SMEM layout (bytes) ----------------
#define WT_DH  0                 // 64 rows x 144B  W2d^T fp16 (Wt[n][k])
#define WT_RH  9216              // W2r^T fp16
#define C_B2D  18432             // 64 f32 each
#define C_B2R  18688
#define C_W3D  18944
#define C_W3R  19200             // 192 f32 col-major [ch*64+n]
#define C_B3   19968             // [0]=bd3, [1..3]=br3
#define SMEM_TOTAL 20096

// ---------------- PTX helpers ----------------
static __device__ __forceinline__ uint32_t smem_u32(const void* p) {
    uint32_t a;
    asm("{ .reg .u64 t; cvta.to.shared.u64 t, %1; cvt.u32.u64 %0, t; }" : "=r"(a) : "l"(p));
    return a;
}
static __device__ __forceinline__ void ldsm_x4(uint32_t* r, uint32_t addr) {
    asm volatile("ldmatrix.sync.aligned.m8n8.x4.shared.b16 {%0,%1,%2,%3}, [%4];"
                 : "=r"(r[0]), "=r"(r[1]), "=r"(r[2]), "=r"(r[3]) : "r"(addr));
}
static __device__ __forceinline__ void mma16816(float* c, const uint32_t* a, const uint32_t* b) {
    asm volatile("mma.sync.aligned.m16n8k16.row.col.f32.f16.f16.f32 "
                 "{%0,%1,%2,%3}, {%4,%5,%6,%7}, {%8,%9}, {%0,%1,%2,%3};"
                 : "+f"(c[0]), "+f"(c[1]), "+f"(c[2]), "+f"(c[3])
                 : "r"(a[0]), "r"(a[1]), "r"(a[2]), "r"(a[3]), "r"(b[0]), "r"(b[1]));
}
static __device__ __forceinline__ void mma16808(float* c, uint32_t a0, uint32_t a1, uint32_t b) {
    asm volatile("mma.sync.aligned.m16n8k8.row.col.f32.f16.f16.f32 "
                 "{%0,%1,%2,%3}, {%4,%5}, {%6}, {%0,%1,%2,%3};"
                 : "+f"(c[0]), "+f"(c[1]), "+f"(c[2]), "+f"(c[3])
                 : "r"(a0), "r"(a1), "r"(b));
}
static __device__ __forceinline__ uint32_t h2_u32(__half2 h) {
    return *reinterpret_cast<uint32_t*>(&h);
}
static __device__ __forceinline__ uint32_t packh2(float lo, float hi) {
    return h2_u32(__floats2half2_rn(lo, hi));
}

// ---------------------------------------------------------------------------
// Per-net register-resident chain:
// L1: 16x m16n8k8 with resident W1 frags (bias folded via the 1.0 column),
// relu+pack -> A-fragments of L2, then L2: 32x m16n8k16 with W2 from smem.
// acc layout identical to previous rounds (rows g+{0,8}+16mb, cols 8n+2t+{0,1}).
// ---------------------------------------------------------------------------
static __device__ __forceinline__ void run_net2(
    uint32_t sb, int bHoff, const uint32_t* w1f,
    const uint32_t* af, uint32_t boff4, float acc[2][8][4])
{
    uint32_t la[2][4][4];   // [mb][kstep][a0..a3]
    #pragma unroll
    for (int mb = 0; mb < 2; mb++) {
        float c[8][4];
        #pragma unroll
        for (int nt = 0; nt < 8; nt++) { c[nt][0]=0.f; c[nt][1]=0.f; c[nt][2]=0.f; c[nt][3]=0.f; }
        #pragma unroll
        for (int nt = 0; nt < 8; nt++)
            mma16808(c[nt], af[2*mb], af[2*mb+1], w1f[nt]);
        #pragma unroll
        for (int k = 0; k < 4; k++) {
            la[mb][k][0] = packh2(fmaxf(c[2*k  ][0],0.f), fmaxf(c[2*k  ][1],0.f));
            la[mb][k][1] = packh2(fmaxf(c[2*k  ][2],0.f), fmaxf(c[2*k  ][3],0.f));
            la[mb][k][2] = packh2(fmaxf(c[2*k+1][0],0.f), fmaxf(c[2*k+1][1],0.f));
            la[mb][k][3] = packh2(fmaxf(c[2*k+1][2],0.f), fmaxf(c[2*k+1][3],0.f));
        }
    }

    #pragma unroll
    for (int mb = 0; mb < 2; mb++)
        #pragma unroll
        for (int n = 0; n < 8; n++)
            #pragma unroll
            for (int e = 0; e < 4; e++) acc[mb][n][e] = 0.0f;

    #pragma unroll
    for (int k = 0; k < 4; k++) {
        #pragma unroll
        for (int np = 0; np < 4; np++) {
            uint32_t b4[4];
            ldsm_x4(b4, sb + bHoff + np * 16 * ASTRIDE + k * 32 + boff4);
            mma16816(acc[0][2*np+0], la[0][k], b4 + 0);
            mma16816(acc[1][2*np+0], la[1][k], b4 + 0);
            mma16816(acc[0][2*np+1], la[0][k], b4 + 2);
            mma16816(acc[1][2*np+1], la[1][k], b4 + 2);
        }
    }
}

// ---------------------------------------------------------------------------
// MLP kernel: persistent single-wave grid, 128-sample tiles, warp-synchronous,
// fully register-resident activations, fused per-ray offset scatter.
// ---------------------------------------------------------------------------
__global__ void __launch_bounds__(128, 4) mlp_tc_kernel(
    const float* __restrict__ rays_o, const float* __restrict__ rays_d,
    const float* __restrict__ t_starts, const float* __restrict__ t_ends,
    const int*   __restrict__ ray_indices,
    const float* __restrict__ Wd1, const float* __restrict__ bd1,
    const float* __restrict__ Wd2, const float* __restrict__ bd2,
    const float* __restrict__ Wd3, const float* __restrict__ bd3,
    const float* __restrict__ Wr1, const float* __restrict__ br1,
    const float* __restrict__ Wr2, const float* __restrict__ br2,
    const float* __restrict__ Wr3, const float* __restrict__ br3)
{
    extern __shared__ char smem[];
    const uint32_t sb = smem_u32(smem);
    const int t    = threadIdx.x;
    const int lane = t & 31;
    const int wid  = t >> 5;
    const int m0   = wid * 32;
    const int g    = lane >> 2;
    const int j    = lane & 3;

    // -------- one-time weight prep (smem: W2 tiles + epilogue constants) ----
    {
        float* w3r = (float*)(smem + C_W3R);
        for (int i = t; i < 192; i += 128)
            w3r[(i % 3) * 64 + (i / 3)] = Wr3[i];     // col-major [ch*64+n]
        if (t < 64) {
            ((float*)(smem + C_B2D))[t] = bd2[t];
            ((float*)(smem + C_B2R))[t] = br2[t];
            ((float*)(smem + C_W3D))[t] = Wd3[t];
        }
        if (t == 0) ((float*)(smem + C_B3))[0] = bd3[0];
        if (t < 3)  ((float*)(smem + C_B3))[1 + t] = br3[t];
        // W2 -> Wt[n][k] = W2[k][n], fp16, stride 144B
        for (int idx = t; idx < 4096; idx += 128) {
            int k = idx >> 6, n = idx & 63;
            int off = n * ASTRIDE + k * 2;
            *(__half*)(smem + WT_DH + off) = __float2half_rn(Wd2[idx]);
            *(__half*)(smem + WT_RH + off) = __float2half_rn(Wr2[idx]);
        }
    }

    // -------- resident W1 B-fragments (bias folded as k=3 row) --------------
    uint32_t w1df[8], w1rf[8];
    #pragma unroll
    for (int nt = 0; nt < 8; nt++) {
        const int col = nt * 8 + g;
        uint32_t vd = 0, vr = 0;
        if (j == 0) {
            vd = packh2(Wd1[col], Wd1[64 + col]);
            vr = packh2(Wr1[col], Wr1[64 + col]);
        } else if (j == 1) {
            vd = packh2(Wd1[128 + col], bd1[col]);
            vr = packh2(Wr1[128 + col], br1[col]);
        }
        w1df[nt] = vd; w1rf[nt] = vr;
    }
    __syncthreads();

    // x4 B ldmatrix per-lane offset (two n-tiles per load)
    const uint32_t boff4 = (uint32_t)(((lane >> 4) & 1) * 8 * ASTRIDE
                                      + (lane & 7) * ASTRIDE + ((lane >> 3) & 1) * 16);

    const float* b2d = (const float*)(smem + C_B2D);
    const float* b2r = (const float*)(smem + C_B2R);
    const float* w3d = (const float*)(smem + C_W3D);
    const float* w3r = (const float*)(smem + C_W3R);
    const float* bb3 = (const float*)(smem + C_B3);

    const int row = m0 + g + 8 * j;   // output row this thread owns

    // -------- persistent tile loop with input prefetch --------
    int tile = blockIdx.x;
    int ri, prev;
    float ts_, te_;
    {
        const int s0 = tile * 128 + t;
        ri   = ray_indices[s0];
        prev = (s0 == 0) ? -1 : ray_indices[s0 - 1];
        ts_  = t_starts[s0];
        te_  = t_ends[s0];
    }

    for (;;) {
        const int tile_n = tile + (int)gridDim.x;
        const bool has_next = tile_n < N_TILES;
        int ri_n = 0, prev_n = 0;
        float ts_n = 0.f, te_n = 0.f;
        if (has_next) {                       // prefetch next tile's inputs
            const int sn = tile_n * 128 + t;
            ri_n   = ray_indices[sn];
            prev_n = ray_indices[sn - 1];     // sn >= 128, safe
            ts_n   = t_starts[sn];
            te_n   = t_ends[sn];
        }

        const int s = tile * 128 + t;

        // fused per-ray offset scatter (ray_indices sorted)
        for (int r = prev + 1; r <= ri; r++) g_off[r] = s;
        if (s == N_SAMPLES - 1)
            for (int r = ri + 1; r <= N_RAYS; r++) g_off[r] = N_SAMPLES;

        const float mid = 0.5f * (ts_ + te_);
        const float dtv = te_ - ts_;
        const float p0 = fmaf(rays_d[ri * 3 + 0], mid, rays_o[ri * 3 + 0]);
        const float p1 = fmaf(rays_d[ri * 3 + 1], mid, rays_o[ri * 3 + 1]);
        const float p2 = fmaf(rays_d[ri * 3 + 2], mid, rays_o[ri * 3 + 2]);

        // -------- build L1 A-fragments + per-row dt via shfl ----------------
        uint32_t af[4];
        float dts[4];
        #pragma unroll
        for (int r4 = 0; r4 < 4; r4++) {
            const int src = g + 8 * r4;
            const float a = __shfl_sync(0xffffffffu, p0, src);
            const float b = __shfl_sync(0xffffffffu, p1, src);
            const float c = __shfl_sync(0xffffffffu, p2, src);
            dts[r4] = __shfl_sync(0xffffffffu, dtv, src);
            const uint32_t v01 = packh2(a, b);
            const uint32_t v21 = packh2(c, 1.0f);
            af[r4] = (j == 0) ? v01 : ((j == 1) ? v21 : 0u);
        }
        const float dtr = (j == 0) ? dts[0] : (j == 1) ? dts[1] : (j == 2) ? dts[2] : dts[3];

        // ================= density net =================
        {
            float acc[2][8][4];
            run_net2(sb, WT_DH, w1df, af, boff4, acc);
            float s0 = 0.f, s1 = 0.f, s2 = 0.f, s3 = 0.f;
            #pragma unroll
            for (int n = 0; n < 8; n++) {
                const int cA = n * 8 + 2 * j;
                const float ba = b2d[cA], bb = b2d[cA + 1];
                const float wa = w3d[cA], wb = w3d[cA + 1];
                s0 = fmaf(fmaxf(acc[0][n][0] + ba, 0.f), wa, fmaf(fmaxf(acc[0][n][1] + bb, 0.f), wb, s0));
                s1 = fmaf(fmaxf(acc[0][n][2] + ba, 0.f), wa, fmaf(fmaxf(acc[0][n][3] + bb, 0.f), wb, s1));
                s2 = fmaf(fmaxf(acc[1][n][0] + ba, 0.f), wa, fmaf(fmaxf(acc[1][n][1] + bb, 0.f), wb, s2));
                s3 = fmaf(fmaxf(acc[1][n][2] + ba, 0.f), wa, fmaf(fmaxf(acc[1][n][3] + bb, 0.f), wb, s3));
            }
            s0 += __shfl_xor_sync(0xffffffffu, s0, 1); s0 += __shfl_xor_sync(0xffffffffu, s0, 2);
            s1 += __shfl_xor_sync(0xffffffffu, s1, 1); s1 += __shfl_xor_sync(0xffffffffu, s1, 2);
            s2 += __shfl_xor_sync(0xffffffffu, s2, 1); s2 += __shfl_xor_sync(0xffffffffu, s2, 2);
            s3 += __shfl_xor_sync(0xffffffffu, s3, 1); s3 += __shfl_xor_sync(0xffffffffu, s3, 2);
            const float sl = ((j == 0) ? s0 : (j == 1) ? s1 : (j == 2) ? s2 : s3) + bb3[0];
            const float sigma = fmaxf(sl, 0.0f) + log1pf(expf(-fabsf(sl)));
            g_sigma_dt[tile * 128 + row] = sigma * dtr;
        }

        // ================= rgb net =================
        {
            float acc[2][8][4];
            run_net2(sb, WT_RH, w1rf, af, boff4, acc);
            float rr[4][3];
            #pragma unroll
            for (int q = 0; q < 4; q++) { rr[q][0] = 0.f; rr[q][1] = 0.f; rr[q][2] = 0.f; }
            #pragma unroll
            for (int n = 0; n < 8; n++) {
                const int cA = n * 8 + 2 * j;
                const float ba = b2r[cA], bb = b2r[cA + 1];
                const float wa0 = w3r[cA],        wb0 = w3r[cA + 1];
                const float wa1 = w3r[64 + cA],   wb1 = w3r[64 + cA + 1];
                const float wa2 = w3r[128 + cA],  wb2 = w3r[128 + cA + 1];
                #pragma unroll
                for (int mb = 0; mb < 2; mb++) {
                    const float hA0 = fmaxf(acc[mb][n][0] + ba, 0.f);
                    const float hB0 = fmaxf(acc[mb][n][1] + bb, 0.f);
                    const float hA1 = fmaxf(acc[mb][n][2] + ba, 0.f);
                    const float hB1 = fmaxf(acc[mb][n][3] + bb, 0.f);
                    rr[mb*2+0][0] = fmaf(hA0, wa0, fmaf(hB0, wb0, rr[mb*2+0][0]));
                    rr[mb*2+0][1] = fmaf(hA0, wa1, fmaf(hB0, wb1, rr[mb*2+0][1]));
                    rr[mb*2+0][2] = fmaf(hA0, wa2, fmaf(hB0, wb2, rr[mb*2+0][2]));
                    rr[mb*2+1][0] = fmaf(hA1, wa0, fmaf(hB1, wb0, rr[mb*2+1][0]));
                    rr[mb*2+1][1] = fmaf(hA1, wa1, fmaf(hB1, wb1, rr[mb*2+1][1]));
                    rr[mb*2+1][2] = fmaf(hA1, wa2, fmaf(hB1, wb2, rr[mb*2+1][2]));
                }
            }
            #pragma unroll
            for (int q = 0; q < 4; q++)
                #pragma unroll
                for (int ch = 0; ch < 3; ch++) {
                    rr[q][ch] += __shfl_xor_sync(0xffffffffu, rr[q][ch], 1);
                    rr[q][ch] += __shfl_xor_sync(0xffffffffu, rr[q][ch], 2);
                }
            const float c0 = ((j==0)?rr[0][0]:(j==1)?rr[1][0]:(j==2)?rr[2][0]:rr[3][0]) + bb3[1];
            const float c1 = ((j==0)?rr[0][1]:(j==1)?rr[1][1]:(j==2)?rr[2][1]:rr[3][1]) + bb3[2];
            const float c2 = ((j==0)?rr[0][2]:(j==1)?rr[1][2]:(j==2)?rr[2][2]:rr[3][2]) + bb3[3];
            const int so = (tile * 128 + row) * 3;
            g_rgb[so + 0] = 1.0f / (1.0f + expf(-c0));
            g_rgb[so + 1] = 1.0f / (1.0f + expf(-c1));
            g_rgb[so + 2] = 1.0f / (1.0f + expf(-c2));
        }

        if (!has_next) break;
        tile = tile_n; ri = ri_n; prev = prev_n; ts_ = ts_n; te_ = te_n;
    }
}

// ---------------------------------------------------------------------------
// Render kernel: one warp per ray, segmented exclusive scan via shfl.
// Output layout: [colors (3R) | distances (R) | opacities (R)].
// ---------------------------------------------------------------------------
__global__ void render_kernel(const float* __restrict__ t_starts,
                              const float* __restrict__ t_ends,
                              float* __restrict__ out)
{
    const int gtid = blockIdx.x * blockDim.x + threadIdx.x;
    const int ray  = gtid >> 5;
    const int lane = threadIdx.x & 31;
    if (ray >= N_RAYS) return;

    const int s = g_off[ray];
    const int e = g_off[ray + 1];

    float carry = 0.0f;
    float op = 0.0f, dist = 0.0f;
    float c0 = 0.0f, c1 = 0.0f, c2 = 0.0f;

    for (int base = s; base < e; base += 32) {
        const int  idx = base + lane;
        const bool v   = (idx < e);
        float sd = v ? g_sigma_dt[idx] : 0.0f;

        float x = sd;
        #pragma unroll
        for (int o = 1; o < 32; o <<= 1) {
            float y = __shfl_up_sync(0xffffffffu, x, o);
            if (lane >= o) x += y;
        }
        const float excl = carry + x - sd;
        carry += __shfl_sync(0xffffffffu, x, 31);

        if (v) {
            const float alpha = -expm1f(-sd);
            const float w     = expf(-excl) * alpha;
            const float m     = 0.5f * (t_starts[idx] + t_ends[idx]);
            op   += w;
            dist += w * m;
            c0 += w * g_rgb[idx * 3 + 0];
            c1 += w * g_rgb[idx * 3 + 1];
            c2 += w * g_rgb[idx * 3 + 2];
        }
    }

    #pragma unroll
    for (int o = 16; o > 0; o >>= 1) {
        op   += __shfl_down_sync(0xffffffffu, op,   o);
        dist += __shfl_down_sync(0xffffffffu, dist, o);
        c0   += __shfl_down_sync(0xffffffffu, c0,   o);
        c1   += __shfl_down_sync(0xffffffffu, c1,   o);
        c2   += __shfl_down_sync(0xffffffffu, c2,   o);
    }

    if (lane == 0) {
        const float rest = 1.0f - op;
        out[ray * 3 + 0] = c0 + 0.5f * rest;
        out[ray * 3 + 1] = c1 + 0.5f * rest;
        out[ray * 3 + 2] = c2 + 0.5f * rest;
        out[3 * N_RAYS + ray] = dist + 5.0f * rest;
        out[4 * N_RAYS + ray] = op;
    }
}

// ---------------------------------------------------------------------------
extern "C" void kernel_launch(void* const* d_in, const int* in_sizes, int n_in,
                              void* d_out, int out_size)
{
    const float* rays_o      = (const float*)d_in[0];
    const float* rays_d      = (const float*)d_in[1];
    const float* t_starts    = (const float*)d_in[2];
    const float* t_ends      = (const float*)d_in[3];
    const int*   ray_indices = (const int*)  d_in[4];
    const float* W_d1 = (const float*)d_in[5];
    const float* b_d1 = (const float*)d_in[6];
    const float* W_d2 = (const float*)d_in[7];
    const float* b_d2 = (const float*)d_in[8];
    const float* W_d3 = (const float*)d_in[9];
    const float* b_d3 = (const float*)d_in[10];
    const float* W_r1 = (const float*)d_in[11];
    const float* b_r1 = (const float*)d_in[12];
    const float* W_r2 = (const float*)d_in[13];
    const float* b_r2 = (const float*)d_in[14];
    const float* W_r3 = (const float*)d_in[15];
    const float* b_r3 = (const float*)d_in[16];
    float* out = (float*)d_out;

    cudaFuncSetAttribute((const void*)mlp_tc_kernel,
                         cudaFuncAttributeMaxDynamicSharedMemorySize, SMEM_TOTAL);

    mlp_tc_kernel<<<GRID_MLP, 128, SMEM_TOTAL>>>(
        rays_o, rays_d, t_starts, t_ends, ray_indices,
        W_d1, b_d1, W_d2, b_d2, W_d3, b_d3,
        W_r1, b_r1, W_r2, b_r2, W_r3, b_r3);

    render_kernel<<<(N_RAYS * 32) / 256, 256>>>(t_starts, t_ends, out);
}

// round 17
// speedup vs baseline: 6.2530x; 1.0024x over previous
#include <cuda_runtime.h>
#include <cuda_fp16.h>
#include <math.h>
#include <stdint.h>

#define N_RAYS 32768
#define N_SAMPLES 1048576
#define N_TILES (N_SAMPLES / 128)
#define GRID_MLP 740             // 148 SMs x 5 CTAs
#define ASTRIDE 144              // 64 fp16 = 128B data + 16B pad

// Scratch (device globals; no allocation anywhere)
__device__ float4 g_out4[N_SAMPLES];   // {sigma_dt, mid, h2(rgb0,rgb1), rgb2}
__device__ int    g_off[N_RAYS + 1];

// ---------------- dynamic SMEM layout (bytes) ----------------
#define WT_DH  0                 // 64 rows x 144B  W2d^T fp16 (Wt[n][k])
#define WT_RH  9216              // W2r^T fp16
#define C_B2D  18432             // 64 f32 each
#define C_B2R  18688
#define C_W3D  18944
#define C_W3R  19200             // 192 f32 col-major [ch*64+n]
#define C_B3   19968             // [0]=bd3, [1..3]=br3
#define SMEM_TOTAL 20096

// ---------------- PTX helpers ----------------
static __device__ __forceinline__ uint32_t smem_u32(const void* p) {
    uint32_t a;
    asm("{ .reg .u64 t; cvta.to.shared.u64 t, %1; cvt.u32.u64 %0, t; }" : "=r"(a) : "l"(p));
    return a;
}
static __device__ __forceinline__ void ldsm_x4(uint32_t* r, uint32_t addr) {
    asm volatile("ldmatrix.sync.aligned.m8n8.x4.shared.b16 {%0,%1,%2,%3}, [%4];"
                 : "=r"(r[0]), "=r"(r[1]), "=r"(r[2]), "=r"(r[3]) : "r"(addr));
}
static __device__ __forceinline__ void mma16816(float* c, const uint32_t* a, const uint32_t* b) {
    asm volatile("mma.sync.aligned.m16n8k16.row.col.f32.f16.f16.f32 "
                 "{%0,%1,%2,%3}, {%4,%5,%6,%7}, {%8,%9}, {%0,%1,%2,%3};"
                 : "+f"(c[0]), "+f"(c[1]), "+f"(c[2]), "+f"(c[3])
                 : "r"(a[0]), "r"(a[1]), "r"(a[2]), "r"(a[3]), "r"(b[0]), "r"(b[1]));
}
static __device__ __forceinline__ void mma16808(float* c, uint32_t a0, uint32_t a1, uint32_t b) {
    asm volatile("mma.sync.aligned.m16n8k8.row.col.f32.f16.f16.f32 "
                 "{%0,%1,%2,%3}, {%4,%5}, {%6}, {%0,%1,%2,%3};"
                 : "+f"(c[0]), "+f"(c[1]), "+f"(c[2]), "+f"(c[3])
                 : "r"(a0), "r"(a1), "r"(b));
}
static __device__ __forceinline__ uint32_t h2_u32(__half2 h) {
    return *reinterpret_cast<uint32_t*>(&h);
}
static __device__ __forceinline__ uint32_t packh2(float lo, float hi) {
    return h2_u32(__floats2half2_rn(lo, hi));
}

// ---------------------------------------------------------------------------
// L1 as MMA (bias folded via the 1.0 column), relu+pack -> L2 A-fragments.
// ---------------------------------------------------------------------------
static __device__ __forceinline__ void build_la(
    uint32_t la[2][4][4], const uint32_t* af, const uint32_t* w1f)
{
    #pragma unroll
    for (int mb = 0; mb < 2; mb++) {
        float c[8][4];
        #pragma unroll
        for (int nt = 0; nt < 8; nt++) { c[nt][0]=0.f; c[nt][1]=0.f; c[nt][2]=0.f; c[nt][3]=0.f; }
        #pragma unroll
        for (int nt = 0; nt < 8; nt++)
            mma16808(c[nt], af[2*mb], af[2*mb+1], w1f[nt]);
        #pragma unroll
        for (int k = 0; k < 4; k++) {
            la[mb][k][0] = packh2(fmaxf(c[2*k  ][0],0.f), fmaxf(c[2*k  ][1],0.f));
            la[mb][k][1] = packh2(fmaxf(c[2*k  ][2],0.f), fmaxf(c[2*k  ][3],0.f));
            la[mb][k][2] = packh2(fmaxf(c[2*k+1][0],0.f), fmaxf(c[2*k+1][1],0.f));
            la[mb][k][3] = packh2(fmaxf(c[2*k+1][2],0.f), fmaxf(c[2*k+1][3],0.f));
        }
    }
}

// ---------------------------------------------------------------------------
// MLP kernel: persistent grid, 128-sample tiles, warp-synchronous, fully
// register-resident activations, np-outer L2 with fused epilogue (small acc),
// bias-folded accumulator init, packed float4 output.
// ---------------------------------------------------------------------------
__global__ void __launch_bounds__(128, 5) mlp_tc_kernel(
    const float* __restrict__ rays_o, const float* __restrict__ rays_d,
    const float* __restrict__ t_starts, const float* __restrict__ t_ends,
    const int*   __restrict__ ray_indices,
    const float* __restrict__ Wd1, const float* __restrict__ bd1,
    const float* __restrict__ Wd2, const float* __restrict__ bd2,
    const float* __restrict__ Wd3, const float* __restrict__ bd3,
    const float* __restrict__ Wr1, const float* __restrict__ br1,
    const float* __restrict__ Wr2, const float* __restrict__ br2,
    const float* __restrict__ Wr3, const float* __restrict__ br3)
{
    extern __shared__ char smem[];
    const uint32_t sb = smem_u32(smem);
    const int t    = threadIdx.x;
    const int lane = t & 31;
    const int wid  = t >> 5;
    const int m0   = wid * 32;
    const int g    = lane >> 2;
    const int j    = lane & 3;

    // -------- one-time weight prep --------
    {
        float* w3r = (float*)(smem + C_W3R);
        for (int i = t; i < 192; i += 128)
            w3r[(i % 3) * 64 + (i / 3)] = Wr3[i];     // col-major [ch*64+n]
        if (t < 64) {
            ((float*)(smem + C_B2D))[t] = bd2[t];
            ((float*)(smem + C_B2R))[t] = br2[t];
            ((float*)(smem + C_W3D))[t] = Wd3[t];
        }
        if (t == 0) ((float*)(smem + C_B3))[0] = bd3[0];
        if (t < 3)  ((float*)(smem + C_B3))[1 + t] = br3[t];
        for (int idx = t; idx < 4096; idx += 128) {
            int k = idx >> 6, n = idx & 63;
            int off = n * ASTRIDE + k * 2;
            *(__half*)(smem + WT_DH + off) = __float2half_rn(Wd2[idx]);
            *(__half*)(smem + WT_RH + off) = __float2half_rn(Wr2[idx]);
        }
    }

    // -------- resident W1 B-fragments (bias folded as k=3 row) --------------
    uint32_t w1df[8], w1rf[8];
    #pragma unroll
    for (int nt = 0; nt < 8; nt++) {
        const int col = nt * 8 + g;
        uint32_t vd = 0, vr = 0;
        if (j == 0) {
            vd = packh2(Wd1[col], Wd1[64 + col]);
            vr = packh2(Wr1[col], Wr1[64 + col]);
        } else if (j == 1) {
            vd = packh2(Wd1[128 + col], bd1[col]);
            vr = packh2(Wr1[128 + col], br1[col]);
        }
        w1df[nt] = vd; w1rf[nt] = vr;
    }
    __syncthreads();

    const uint32_t boff4 = (uint32_t)(((lane >> 4) & 1) * 8 * ASTRIDE
                                      + (lane & 7) * ASTRIDE + ((lane >> 3) & 1) * 16);

    const float* b2d = (const float*)(smem + C_B2D);
    const float* b2r = (const float*)(smem + C_B2R);
    const float* w3d = (const float*)(smem + C_W3D);
    const float* w3r = (const float*)(smem + C_W3R);
    const float* bb3 = (const float*)(smem + C_B3);

    const int row = m0 + g + 8 * j;   // output row this thread owns

    // -------- persistent tile loop with input prefetch --------
    int tile = blockIdx.x;
    int ri, prev;
    float ts_, te_;
    {
        const int s0 = tile * 128 + t;
        ri   = ray_indices[s0];
        prev = (s0 == 0) ? -1 : ray_indices[s0 - 1];
        ts_  = t_starts[s0];
        te_  = t_ends[s0];
    }

    for (;;) {
        const int tile_n = tile + (int)gridDim.x;
        const bool has_next = tile_n < N_TILES;
        int ri_n = 0, prev_n = 0;
        float ts_n = 0.f, te_n = 0.f;
        if (has_next) {
            const int sn = tile_n * 128 + t;
            ri_n   = ray_indices[sn];
            prev_n = ray_indices[sn - 1];
            ts_n   = t_starts[sn];
            te_n   = t_ends[sn];
        }

        const int s = tile * 128 + t;

        // fused per-ray offset scatter (ray_indices sorted)
        for (int r = prev + 1; r <= ri; r++) g_off[r] = s;
        if (s == N_SAMPLES - 1)
            for (int r = ri + 1; r <= N_RAYS; r++) g_off[r] = N_SAMPLES;

        const float mid = 0.5f * (ts_ + te_);
        const float dtv = te_ - ts_;
        const float p0 = fmaf(rays_d[ri * 3 + 0], mid, rays_o[ri * 3 + 0]);
        const float p1 = fmaf(rays_d[ri * 3 + 1], mid, rays_o[ri * 3 + 1]);
        const float p2 = fmaf(rays_d[ri * 3 + 2], mid, rays_o[ri * 3 + 2]);

        // -------- L1 A-fragments + per-row dt/mid via shfl ------------------
        uint32_t af[4];
        float dtr = 0.f, midr = 0.f;
        #pragma unroll
        for (int r4 = 0; r4 < 4; r4++) {
            const int src = g + 8 * r4;
            const float a = __shfl_sync(0xffffffffu, p0, src);
            const float b = __shfl_sync(0xffffffffu, p1, src);
            const float c = __shfl_sync(0xffffffffu, p2, src);
            const float d = __shfl_sync(0xffffffffu, dtv, src);
            const float m = __shfl_sync(0xffffffffu, mid, src);
            if (r4 == j) { dtr = d; midr = m; }
            const uint32_t v01 = packh2(a, b);
            const uint32_t v21 = packh2(c, 1.0f);
            af[r4] = (j == 0) ? v01 : ((j == 1) ? v21 : 0u);
        }

        float sdv;
        // ================= density net =================
        {
            uint32_t la[2][4][4];
            build_la(la, af, w1df);
            float s0 = 0.f, s1 = 0.f, s2 = 0.f, s3 = 0.f;
            #pragma unroll
            for (int np = 0; np < 4; np++) {
                const int c0i = 16 * np + 2 * j;
                const int c1i = c0i + 8;
                const float ba0 = b2d[c0i], bb0 = b2d[c0i + 1];
                const float ba1 = b2d[c1i], bb1 = b2d[c1i + 1];
                float acc[2][2][4];
                #pragma unroll
                for (int mb = 0; mb < 2; mb++) {
                    acc[mb][0][0] = ba0; acc[mb][0][1] = bb0; acc[mb][0][2] = ba0; acc[mb][0][3] = bb0;
                    acc[mb][1][0] = ba1; acc[mb][1][1] = bb1; acc[mb][1][2] = ba1; acc[mb][1][3] = bb1;
                }
                #pragma unroll
                for (int k = 0; k < 4; k++) {
                    uint32_t b4[4];
                    ldsm_x4(b4, sb + WT_DH + np * 16 * ASTRIDE + k * 32 + boff4);
                    mma16816(acc[0][0], la[0][k], b4 + 0);
                    mma16816(acc[1][0], la[1][k], b4 + 0);
                    mma16816(acc[0][1], la[0][k], b4 + 2);
                    mma16816(acc[1][1], la[1][k], b4 + 2);
                }
                const float wa0 = w3d[c0i], wb0 = w3d[c0i + 1];
                const float wa1 = w3d[c1i], wb1 = w3d[c1i + 1];
                s0 = fmaf(fmaxf(acc[0][0][0],0.f), wa0, fmaf(fmaxf(acc[0][0][1],0.f), wb0,
                     fmaf(fmaxf(acc[0][1][0],0.f), wa1, fmaf(fmaxf(acc[0][1][1],0.f), wb1, s0))));
                s1 = fmaf(fmaxf(acc[0][0][2],0.f), wa0, fmaf(fmaxf(acc[0][0][3],0.f), wb0,
                     fmaf(fmaxf(acc[0][1][2],0.f), wa1, fmaf(fmaxf(acc[0][1][3],0.f), wb1, s1))));
                s2 = fmaf(fmaxf(acc[1][0][0],0.f), wa0, fmaf(fmaxf(acc[1][0][1],0.f), wb0,
                     fmaf(fmaxf(acc[1][1][0],0.f), wa1, fmaf(fmaxf(acc[1][1][1],0.f), wb1, s2))));
                s3 = fmaf(fmaxf(acc[1][0][2],0.f), wa0, fmaf(fmaxf(acc[1][0][3],0.f), wb0,
                     fmaf(fmaxf(acc[1][1][2],0.f), wa1, fmaf(fmaxf(acc[1][1][3],0.f), wb1, s3))));
            }
            s0 += __shfl_xor_sync(0xffffffffu, s0, 1); s0 += __shfl_xor_sync(0xffffffffu, s0, 2);
            s1 += __shfl_xor_sync(0xffffffffu, s1, 1); s1 += __shfl_xor_sync(0xffffffffu, s1, 2);
            s2 += __shfl_xor_sync(0xffffffffu, s2, 1); s2 += __shfl_xor_sync(0xffffffffu, s2, 2);
            s3 += __shfl_xor_sync(0xffffffffu, s3, 1); s3 += __shfl_xor_sync(0xffffffffu, s3, 2);
            const float sl = ((j == 0) ? s0 : (j == 1) ? s1 : (j == 2) ? s2 : s3) + bb3[0];
            const float sigma = fmaxf(sl, 0.0f) + log1pf(expf(-fabsf(sl)));
            sdv = sigma * dtr;
        }

        // ================= rgb net =================
        {
            uint32_t la[2][4][4];
            build_la(la, af, w1rf);
            float rr[4][3];
            #pragma unroll
            for (int q = 0; q < 4; q++) { rr[q][0] = 0.f; rr[q][1] = 0.f; rr[q][2] = 0.f; }
            #pragma unroll
            for (int np = 0; np < 4; np++) {
                const int c0i = 16 * np + 2 * j;
                const int c1i = c0i + 8;
                const float ba0 = b2r[c0i], bb0 = b2r[c0i + 1];
                const float ba1 = b2r[c1i], bb1 = b2r[c1i + 1];
                float acc[2][2][4];
                #pragma unroll
                for (int mb = 0; mb < 2; mb++) {
                    acc[mb][0][0] = ba0; acc[mb][0][1] = bb0; acc[mb][0][2] = ba0; acc[mb][0][3] = bb0;
                    acc[mb][1][0] = ba1; acc[mb][1][1] = bb1; acc[mb][1][2] = ba1; acc[mb][1][3] = bb1;
                }
                #pragma unroll
                for (int k = 0; k < 4; k++) {
                    uint32_t b4[4];
                    ldsm_x4(b4, sb + WT_RH + np * 16 * ASTRIDE + k * 32 + boff4);
                    mma16816(acc[0][0], la[0][k], b4 + 0);
                    mma16816(acc[1][0], la[1][k], b4 + 0);
                    mma16816(acc[0][1], la[0][k], b4 + 2);
                    mma16816(acc[1][1], la[1][k], b4 + 2);
                }
                #pragma unroll
                for (int ch = 0; ch < 3; ch++) {
                    const float wa0 = w3r[ch * 64 + c0i], wb0 = w3r[ch * 64 + c0i + 1];
                    const float wa1 = w3r[ch * 64 + c1i], wb1 = w3r[ch * 64 + c1i + 1];
                    rr[0][ch] = fmaf(fmaxf(acc[0][0][0],0.f), wa0, fmaf(fmaxf(acc[0][0][1],0.f), wb0,
                                fmaf(fmaxf(acc[0][1][0],0.f), wa1, fmaf(fmaxf(acc[0][1][1],0.f), wb1, rr[0][ch]))));
                    rr[1][ch] = fmaf(fmaxf(acc[0][0][2],0.f), wa0, fmaf(fmaxf(acc[0][0][3],0.f), wb0,
                                fmaf(fmaxf(acc[0][1][2],0.f), wa1, fmaf(fmaxf(acc[0][1][3],0.f), wb1, rr[1][ch]))));
                    rr[2][ch] = fmaf(fmaxf(acc[1][0][0],0.f), wa0, fmaf(fmaxf(acc[1][0][1],0.f), wb0,
                                fmaf(fmaxf(acc[1][1][0],0.f), wa1, fmaf(fmaxf(acc[1][1][1],0.f), wb1, rr[2][ch]))));
                    rr[3][ch] = fmaf(fmaxf(acc[1][0][2],0.f), wa0, fmaf(fmaxf(acc[1][0][3],0.f), wb0,
                                fmaf(fmaxf(acc[1][1][2],0.f), wa1, fmaf(fmaxf(acc[1][1][3],0.f), wb1, rr[3][ch]))));
                }
            }
            #pragma unroll
            for (int q = 0; q < 4; q++)
                #pragma unroll
                for (int ch = 0; ch < 3; ch++) {
                    rr[q][ch] += __shfl_xor_sync(0xffffffffu, rr[q][ch], 1);
                    rr[q][ch] += __shfl_xor_sync(0xffffffffu, rr[q][ch], 2);
                }
            const float c0 = ((j==0)?rr[0][0]:(j==1)?rr[1][0]:(j==2)?rr[2][0]:rr[3][0]) + bb3[1];
            const float c1 = ((j==0)?rr[0][1]:(j==1)?rr[1][1]:(j==2)?rr[2][1]:rr[3][1]) + bb3[2];
            const float c2 = ((j==0)?rr[0][2]:(j==1)?rr[1][2]:(j==2)?rr[2][2]:rr[3][2]) + bb3[3];
            const float e0 = 1.0f / (1.0f + expf(-c0));
            const float e1 = 1.0f / (1.0f + expf(-c1));
            const float e2 = 1.0f / (1.0f + expf(-c2));
            float4 v;
            v.x = sdv;
            v.y = midr;
            v.z = __uint_as_float(packh2(e0, e1));
            v.w = e2;
            g_out4[tile * 128 + row] = v;
        }

        if (!has_next) break;
        tile = tile_n; ri = ri_n; prev = prev_n; ts_ = ts_n; te_ = te_n;
    }
}

// ---------------------------------------------------------------------------
// Render kernel: one warp per ray, segmented exclusive scan via shfl.
// Reads packed float4 {sigma_dt, mid, h2(rgb0,rgb1), rgb2}.
// Output layout: [colors (3R) | distances (R) | opacities (R)].
// ---------------------------------------------------------------------------
__global__ void render_kernel(float* __restrict__ out)
{
    const int gtid = blockIdx.x * blockDim.x + threadIdx.x;
    const int ray  = gtid >> 5;
    const int lane = threadIdx.x & 31;
    if (ray >= N_RAYS) return;

    const int s = g_off[ray];
    const int e = g_off[ray + 1];

    float carry = 0.0f;
    float op = 0.0f, dist = 0.0f;
    float c0 = 0.0f, c1 = 0.0f, c2 = 0.0f;

    for (int base = s; base < e; base += 32) {
        const int  idx = base + lane;
        const bool v   = (idx < e);
        float4 pk = v ? g_out4[idx] : make_float4(0.f, 0.f, 0.f, 0.f);
        const float sd = pk.x;

        float x = sd;
        #pragma unroll
        for (int o = 1; o < 32; o <<= 1) {
            float y = __shfl_up_sync(0xffffffffu, x, o);
            if (lane >= o) x += y;
        }
        const float excl = carry + x - sd;
        carry += __shfl_sync(0xffffffffu, x, 31);

        if (v) {
            const float alpha = -expm1f(-sd);
            const float w     = expf(-excl) * alpha;
            __half2 rgb01 = *reinterpret_cast<__half2*>(&pk.z);
            float2 r01 = __half22float2(rgb01);
            op   += w;
            dist += w * pk.y;
            c0 += w * r01.x;
            c1 += w * r01.y;
            c2 += w * pk.w;
        }
    }

    #pragma unroll
    for (int o = 16; o > 0; o >>= 1) {
        op   += __shfl_down_sync(0xffffffffu, op,   o);
        dist += __shfl_down_sync(0xffffffffu, dist, o);
        c0   += __shfl_down_sync(0xffffffffu, c0,   o);
        c1   += __shfl_down_sync(0xffffffffu, c1,   o);
        c2   += __shfl_down_sync(0xffffffffu, c2,   o);
    }

    if (lane == 0) {
        const float rest = 1.0f - op;
        out[ray * 3 + 0] = c0 + 0.5f * rest;
        out[ray * 3 + 1] = c1 + 0.5f * rest;
        out[ray * 3 + 2] = c2 + 0.5f * rest;
        out[3 * N_RAYS + ray] = dist + 5.0f * rest;
        out[4 * N_RAYS + ray] = op;
    }
}

// ---------------------------------------------------------------------------
extern "C" void kernel_launch(void* const* d_in, const int* in_sizes, int n_in,
                              void* d_out, int out_size)
{
    const float* rays_o      = (const float*)d_in[0];
    const float* rays_d      = (const float*)d_in[1];
    const float* t_starts    = (const float*)d_in[2];
    const float* t_ends      = (const float*)d_in[3];
    const int*   ray_indices = (const int*)  d_in[4];
    const float* W_d1 = (const float*)d_in[5];
    const float* b_d1 = (const float*)d_in[6];
    const float* W_d2 = (const float*)d_in[7];
    const float* b_d2 = (const float*)d_in[8];
    const float* W_d3 = (const float*)d_in[9];
    const float* b_d3 = (const float*)d_in[10];
    const float* W_r1 = (const float*)d_in[11];
    const float* b_r1 = (const float*)d_in[12];
    const float* W_r2 = (const float*)d_in[13];
    const float* b_r2 = (const float*)d_in[14];
    const float* W_r3 = (const float*)d_in[15];
    const float* b_r3 = (const float*)d_in[16];
    float* out = (float*)d_out;

    cudaFuncSetAttribute((const void*)mlp_tc_kernel,
                         cudaFuncAttributeMaxDynamicSharedMemorySize, SMEM_TOTAL);

    mlp_tc_kernel<<<GRID_MLP, 128, SMEM_TOTAL>>>(
        rays_o, rays_d, t_starts, t_ends, ray_indices,
        W_d1, b_d1, W_d2, b_d2, W_d3, b_d3,
        W_r1, b_r1, W_r2, b_r2, W_r3, b_r3);

    render_kernel<<<(N_RAYS * 32) / 256, 256>>>(out);
}